// round 2
// baseline (speedup 1.0000x reference)
#include <cuda_runtime.h>

typedef unsigned long long u64;

__device__ __forceinline__ u64 f2fma(u64 a, u64 b, u64 c) {
    u64 d;
    asm("fma.rn.f32x2 %0, %1, %2, %3;" : "=l"(d) : "l"(a), "l"(b), "l"(c));
    return d;
}
__device__ __forceinline__ u64 f2bcast(float x) {
    u64 d;
    asm("mov.b64 %0, {%1, %1};" : "=l"(d) : "f"(x));
    return d;
}
__device__ __forceinline__ float2 f2unpack(u64 v) {
    float2 r;
    asm("mov.b64 {%0, %1}, %2;" : "=f"(r.x), "=f"(r.y) : "l"(v));
    return r;
}
__device__ __forceinline__ float hswish(float x) {
    return x * __saturatef((x + 3.0f) * (1.0f / 6.0f));
}

#define P_TOTAL 409600

// Scratch (device globals: allocation-free per harness rules)
__device__ float g_y [P_TOTAL * 64];
__device__ float g_t [P_TOTAL * 64];
__device__ float g_xc[P_TOTAL * 128];

// ---------------------------------------------------------------------------
// 1x1 conv as GEMM. 256 threads. Each thread: PX=4 pixels x 16 out-channels
// (32 f32x2 accumulators). Inputs + weights staged in padded smem.
//   EPI: 0 = plain conv, 1 = BN + hard-swish
//   PRE: apply bn_cat + LeakyReLU(0.1) to inputs while staging (cv4 path)
// Smem padding: input row stride CIN+4 (banks 0,4,..,28 across warp slots),
// weight 16-float co-blocks padded to 20 (cog*20 mod 32 spreads all lanes).
// ---------------------------------------------------------------------------
template<int CIN, int COUT, int EPI, bool PRE>
__global__ void __launch_bounds__(256, 1) conv1x1_k(
    const float* __restrict__ in, const float* __restrict__ w,
    const float* __restrict__ bnp, const float* __restrict__ prebn,
    float* __restrict__ out, int ostride, int ocoff)
{
    constexpr int G    = COUT / 16;       // co-groups
    constexpr int S    = 256 / G;         // pixel slots
    constexpr int PX   = 4;
    constexpr int TP   = S * PX;          // pixels per block
    constexpr int CSTR = CIN + 4;
    constexpr int WSTR = COUT + (COUT / 16) * 4;

    extern __shared__ float sm[];
    float* in_s  = sm;                    // TP * CSTR
    float* w_s   = sm + TP * CSTR;        // CIN * WSTR
    float* pre_s = w_s + CIN * WSTR;      // 2 * CIN (PRE only)

    const int tid = threadIdx.x;
    const long long p0 = (long long)blockIdx.x * TP;

    if (PRE) {
        if (tid < CIN) {
            float g = prebn[tid], b = prebn[CIN + tid];
            float m = prebn[2 * CIN + tid], v = prebn[3 * CIN + tid];
            float sc = g * rsqrtf(v + 1e-3f);
            pre_s[tid]       = sc;
            pre_s[CIN + tid] = b - m * sc;
        }
        __syncthreads();
    }

    // stage weights (HWIO 1x1 => [CIN][COUT], COUT contiguous)
    constexpr int C4O = COUT / 4;
    for (int i = tid; i < CIN * C4O; i += 256) {
        int ci = i / C4O, c4 = i - ci * C4O;
        int co = c4 * 4;
        float4 v = ((const float4*)w)[i];
        *(float4*)&w_s[ci * WSTR + co + ((co >> 4) << 2)] = v;
    }

    // stage inputs
    constexpr int C4 = CIN / 4;
    for (int i = tid; i < TP * C4; i += 256) {
        int p = i / C4, c4 = i - p * C4;
        float4 v = ((const float4*)(in + (p0 + p) * CIN))[c4];
        if (PRE) {
            int c = c4 * 4;
            float t;
            t = pre_s[c+0]*v.x + pre_s[CIN+c+0]; v.x = t >= 0.f ? t : 0.1f*t;
            t = pre_s[c+1]*v.y + pre_s[CIN+c+1]; v.y = t >= 0.f ? t : 0.1f*t;
            t = pre_s[c+2]*v.z + pre_s[CIN+c+2]; v.z = t >= 0.f ? t : 0.1f*t;
            t = pre_s[c+3]*v.w + pre_s[CIN+c+3]; v.w = t >= 0.f ? t : 0.1f*t;
        }
        *(float4*)&in_s[p * CSTR + c4 * 4] = v;
    }
    __syncthreads();

    const int slot = tid / G;
    const int cog  = tid - slot * G;

    u64 acc[PX][8];
    #pragma unroll
    for (int i = 0; i < PX; i++)
        #pragma unroll
        for (int j = 0; j < 8; j++) acc[i][j] = 0ull;

    const float* wb = w_s + cog * 20;
    #pragma unroll 2
    for (int k = 0; k < CIN; k += 4) {
        float4 a[PX];
        #pragma unroll
        for (int i = 0; i < PX; i++)
            a[i] = *(const float4*)&in_s[(slot + i * S) * CSTR + k];
        #pragma unroll
        for (int kk = 0; kk < 4; kk++) {
            const ulonglong2* wr = (const ulonglong2*)(wb + (k + kk) * WSTR);
            u64 wv[8];
            #pragma unroll
            for (int j = 0; j < 4; j++) {
                ulonglong2 q = wr[j];
                wv[2*j] = q.x; wv[2*j+1] = q.y;
            }
            #pragma unroll
            for (int i = 0; i < PX; i++) {
                float av = (kk == 0) ? a[i].x : (kk == 1) ? a[i].y
                         : (kk == 2) ? a[i].z : a[i].w;
                u64 ab = f2bcast(av);
                #pragma unroll
                for (int j = 0; j < 8; j++) acc[i][j] = f2fma(ab, wv[j], acc[i][j]);
            }
        }
    }

    float scl[16], bia[16];
    if (EPI == 1) {
        #pragma unroll
        for (int j = 0; j < 16; j++) {
            int c = cog * 16 + j;
            float g = bnp[c], b = bnp[COUT + c];
            float m = bnp[2 * COUT + c], v = bnp[3 * COUT + c];
            scl[j] = g * rsqrtf(v + 1e-3f);
            bia[j] = b - m * scl[j];
        }
    }
    #pragma unroll
    for (int i = 0; i < PX; i++) {
        long long p = p0 + slot + i * S;
        float o[16];
        #pragma unroll
        for (int j = 0; j < 8; j++) {
            float2 v = f2unpack(acc[i][j]);
            o[2*j] = v.x; o[2*j+1] = v.y;
        }
        if (EPI == 1) {
            #pragma unroll
            for (int j = 0; j < 16; j++) {
                float t = scl[j] * o[j] + bia[j];
                o[j] = hswish(t);
            }
        }
        float* op = out + p * ostride + ocoff + cog * 16;
        #pragma unroll
        for (int j = 0; j < 4; j++)
            *(float4*)(op + 4*j) = make_float4(o[4*j], o[4*j+1], o[4*j+2], o[4*j+3]);
    }
}

// ---------------------------------------------------------------------------
// 3x3 SAME conv (64->64) + BN + hard-swish + residual add into yio.
// One block = 16x16 spatial tile of one image; halo tile (18x18x64) in smem,
// 9 taps each staging a 64x64 weight slice. Same register tiling as 1x1.
// ---------------------------------------------------------------------------
__global__ void __launch_bounds__(256, 1) conv3x3_res_k(
    const float* __restrict__ in, const float* __restrict__ w,
    const float* __restrict__ bnp, float* __restrict__ yio)
{
    constexpr int CSTR = 68;
    constexpr int WSTR = 80;
    extern __shared__ float sm[];
    float* in_s = sm;               // 324 * 68
    float* w_s  = sm + 324 * CSTR;  // 64 * 80

    const int tid = threadIdx.x;
    const int blk = blockIdx.x;              // 16 images * 10 * 10 tiles
    const int b  = blk / 100;
    const int t  = blk - b * 100;
    const int ty = t / 10, tx = t - ty * 10;
    const int y0 = ty * 16, x0 = tx * 16;
    const long long img = (long long)b * 25600;

    // load 18x18 halo tile (zero padded)
    for (int i = tid; i < 324 * 16; i += 256) {
        int r = i >> 4, c4 = i & 15;
        int iy = r / 18, ix = r - iy * 18;
        int gy = y0 + iy - 1, gx = x0 + ix - 1;
        float4 v = make_float4(0.f, 0.f, 0.f, 0.f);
        if (gy >= 0 && gy < 160 && gx >= 0 && gx < 160)
            v = ((const float4*)(in + (img + gy * 160 + gx) * 64))[c4];
        *(float4*)&in_s[r * CSTR + c4 * 4] = v;
    }

    const int slot = tid >> 2;
    const int cog  = tid & 3;

    int py[4], px[4];
    #pragma unroll
    for (int i = 0; i < 4; i++) {
        int p = slot + i * 64;
        py[i] = p >> 4; px[i] = p & 15;
    }

    u64 acc[4][8];
    #pragma unroll
    for (int i = 0; i < 4; i++)
        #pragma unroll
        for (int j = 0; j < 8; j++) acc[i][j] = 0ull;

    for (int tap = 0; tap < 9; tap++) {
        __syncthreads();   // also covers initial halo-load completion
        for (int i = tid; i < 1024; i += 256) {
            int ci = i >> 4, c4 = i & 15;
            int co = c4 * 4;
            float4 v = ((const float4*)(w + tap * 4096))[i];
            *(float4*)&w_s[ci * WSTR + co + ((co >> 4) << 2)] = v;
        }
        __syncthreads();
        const int kh = tap / 3, kw = tap - kh * 3;
        int rb[4];
        #pragma unroll
        for (int i = 0; i < 4; i++)
            rb[i] = ((py[i] + kh) * 18 + px[i] + kw) * CSTR;

        const float* wb = w_s + cog * 20;
        #pragma unroll 2
        for (int k = 0; k < 64; k += 4) {
            float4 a[4];
            #pragma unroll
            for (int i = 0; i < 4; i++)
                a[i] = *(const float4*)&in_s[rb[i] + k];
            #pragma unroll
            for (int kk = 0; kk < 4; kk++) {
                const ulonglong2* wr = (const ulonglong2*)(wb + (k + kk) * WSTR);
                u64 wv[8];
                #pragma unroll
                for (int j = 0; j < 4; j++) {
                    ulonglong2 q = wr[j];
                    wv[2*j] = q.x; wv[2*j+1] = q.y;
                }
                #pragma unroll
                for (int i = 0; i < 4; i++) {
                    float av = (kk == 0) ? a[i].x : (kk == 1) ? a[i].y
                             : (kk == 2) ? a[i].z : a[i].w;
                    u64 ab = f2bcast(av);
                    #pragma unroll
                    for (int j = 0; j < 8; j++) acc[i][j] = f2fma(ab, wv[j], acc[i][j]);
                }
            }
        }
    }

    float scl[16], bia[16];
    #pragma unroll
    for (int j = 0; j < 16; j++) {
        int c = cog * 16 + j;
        float g = bnp[c], b2 = bnp[64 + c];
        float m = bnp[128 + c], v = bnp[192 + c];
        scl[j] = g * rsqrtf(v + 1e-3f);
        bia[j] = b2 - m * scl[j];
    }
    #pragma unroll
    for (int i = 0; i < 4; i++) {
        long long gp = img + (long long)(y0 + py[i]) * 160 + (x0 + px[i]);
        float* yp = yio + gp * 64 + cog * 16;
        float o[16];
        #pragma unroll
        for (int j = 0; j < 8; j++) {
            float2 v = f2unpack(acc[i][j]);
            o[2*j] = v.x; o[2*j+1] = v.y;
        }
        #pragma unroll
        for (int j = 0; j < 16; j++) {
            float t2 = scl[j] * o[j] + bia[j];
            o[j] = hswish(t2);
        }
        #pragma unroll
        for (int j = 0; j < 4; j++) {
            float4 r = *(float4*)(yp + 4*j);
            r.x += o[4*j+0]; r.y += o[4*j+1];
            r.z += o[4*j+2]; r.w += o[4*j+3];
            *(float4*)(yp + 4*j) = r;
        }
    }
}

// ---------------------------------------------------------------------------

extern "C" void kernel_launch(void* const* d_in, const int* in_sizes, int n_in,
                              void* d_out, int out_size)
{
    (void)in_sizes; (void)n_in; (void)out_size;
    const float* x         = (const float*)d_in[0];
    const float* cv1_w     = (const float*)d_in[1];
    const float* cv1_bn    = (const float*)d_in[2];
    const float* m0_cv1_w  = (const float*)d_in[3];
    const float* m0_cv1_bn = (const float*)d_in[4];
    const float* m0_cv2_w  = (const float*)d_in[5];
    const float* m0_cv2_bn = (const float*)d_in[6];
    const float* m1_cv1_w  = (const float*)d_in[7];
    const float* m1_cv1_bn = (const float*)d_in[8];
    const float* m1_cv2_w  = (const float*)d_in[9];
    const float* m1_cv2_bn = (const float*)d_in[10];
    const float* cv3_w     = (const float*)d_in[11];
    const float* cv2p_w    = (const float*)d_in[12];
    const float* bn_cat    = (const float*)d_in[13];
    const float* cv4_w     = (const float*)d_in[14];
    const float* cv4_bn    = (const float*)d_in[15];
    float* out = (float*)d_out;

    float *py = nullptr, *pt = nullptr, *pxc = nullptr;
    cudaGetSymbolAddress((void**)&py,  g_y);
    cudaGetSymbolAddress((void**)&pt,  g_t);
    cudaGetSymbolAddress((void**)&pxc, g_xc);

    constexpr int SM_A = (256*132 + 128*80) * 4;            // 176128 B
    constexpr int SM_B = (256*68  + 64*80)  * 4;            //  90112 B
    constexpr int SM_C = (324*68  + 64*80)  * 4;            // 108608 B
    constexpr int SM_D = (128*132 + 128*160 + 256) * 4;     // 150528 B

    cudaFuncSetAttribute(conv1x1_k<128, 64,1,false>, cudaFuncAttributeMaxDynamicSharedMemorySize, SM_A);
    cudaFuncSetAttribute(conv1x1_k< 64, 64,1,false>, cudaFuncAttributeMaxDynamicSharedMemorySize, SM_B);
    cudaFuncSetAttribute(conv1x1_k< 64, 64,0,false>, cudaFuncAttributeMaxDynamicSharedMemorySize, SM_B);
    cudaFuncSetAttribute(conv1x1_k<128, 64,0,false>, cudaFuncAttributeMaxDynamicSharedMemorySize, SM_A);
    cudaFuncSetAttribute(conv1x1_k<128,128,1,true >, cudaFuncAttributeMaxDynamicSharedMemorySize, SM_D);
    cudaFuncSetAttribute(conv3x3_res_k,              cudaFuncAttributeMaxDynamicSharedMemorySize, SM_C);

    // cv1: 1x1 128->64, BN+hswish
    conv1x1_k<128,64,1,false><<<1600, 256, SM_A>>>(x,  cv1_w,    cv1_bn,    nullptr, py, 64, 0);
    // bottleneck 0
    conv1x1_k< 64,64,1,false><<<1600, 256, SM_B>>>(py, m0_cv1_w, m0_cv1_bn, nullptr, pt, 64, 0);
    conv3x3_res_k<<<1600, 256, SM_C>>>(pt, m0_cv2_w, m0_cv2_bn, py);
    // bottleneck 1
    conv1x1_k< 64,64,1,false><<<1600, 256, SM_B>>>(py, m1_cv1_w, m1_cv1_bn, nullptr, pt, 64, 0);
    conv3x3_res_k<<<1600, 256, SM_C>>>(pt, m1_cv2_w, m1_cv2_bn, py);
    // x1 = conv1x1(y, cv3_w) -> xc[:, 0:64]   (plain conv)
    conv1x1_k< 64,64,0,false><<<1600, 256, SM_B>>>(py, cv3_w,  nullptr, nullptr, pxc, 128, 0);
    // x2 = conv1x1(x, cv2p_w) -> xc[:, 64:128] (plain conv)
    conv1x1_k<128,64,0,false><<<1600, 256, SM_A>>>(x,  cv2p_w, nullptr, nullptr, pxc, 128, 64);
    // cv4: bn_cat+leaky on input, 1x1 128->128, BN+hswish -> out
    conv1x1_k<128,128,1,true><<<3200, 256, SM_D>>>(pxc, cv4_w, cv4_bn, bn_cat, out, 128, 0);
}

// round 4
// speedup vs baseline: 1.2397x; 1.2397x over previous
#include <cuda_runtime.h>
#include <cuda_fp16.h>
#include <cstdint>

typedef unsigned short u16;
typedef unsigned int   u32;

// ─── helpers ───────────────────────────────────────────────────────────────
__device__ __forceinline__ u32 smem_u32(const void* p){
    u32 a;
    asm("{ .reg .u64 t; cvta.to.shared.u64 t, %1; cvt.u32.u64 %0, t; }"
        : "=r"(a) : "l"(p));
    return a;
}
__device__ __forceinline__ void ldsm4(u32 addr, u32& r0, u32& r1, u32& r2, u32& r3){
    asm volatile("ldmatrix.sync.aligned.m8n8.x4.shared.b16 {%0,%1,%2,%3}, [%4];"
        : "=r"(r0), "=r"(r1), "=r"(r2), "=r"(r3) : "r"(addr));
}
__device__ __forceinline__ void mma_(float* c, const u32* a, u32 b0, u32 b1){
    asm volatile("mma.sync.aligned.m16n8k16.row.col.f32.f16.f16.f32 "
        "{%0,%1,%2,%3},{%4,%5,%6,%7},{%8,%9},{%0,%1,%2,%3};"
        : "+f"(c[0]), "+f"(c[1]), "+f"(c[2]), "+f"(c[3])
        : "r"(a[0]), "r"(a[1]), "r"(a[2]), "r"(a[3]), "r"(b0), "r"(b1));
}
// split (a,b) fp32 -> fp16 hi pair + fp16 lo (residual) pair
__device__ __forceinline__ void sp2(float a, float b, u32& H, u32& L){
    __half2 h = __floats2half2_rn(a, b);
    float2 hf = __half22float2(h);
    __half2 l = __floats2half2_rn(a - hf.x, b - hf.y);
    H = *(u32*)&h; L = *(u32*)&l;
}
__device__ __forceinline__ float2 dec(u32 v){
    __half2 h = *(__half2*)&v; return __half22float2(h);
}
__device__ __forceinline__ float hswish(float x){
    return x * __saturatef((x + 3.0f) * (1.0f / 6.0f));
}

// ─── global scratch ────────────────────────────────────────────────────────
#define PXT 409600
#define TPAD (16*162*162)
#define WTOT 118784

__device__ __align__(16) u16 g_yh[PXT*64], g_yl[PXT*64];
__device__ __align__(16) u16 g_ah[PXT*64], g_al[PXT*64];
__device__ __align__(16) u16 g_bh[PXT*64], g_bl[PXT*64];
__device__ __align__(16) u16 g_th[TPAD*64], g_tl[TPAD*64];
__device__ __align__(16) u16 g_wh[WTOT], g_wl[WTOT];
__device__ float g_sb[1280];

#define WO_CV1   0
#define WO_M0A   8192
#define WO_M0B   12288
#define WO_M1A   49152
#define WO_M1B   53248
#define WO_CV3   90112
#define WO_CV2P  94208
#define WO_CV4   102400

#define SB_CV1   0
#define SB_M0A   128
#define SB_M0B   256
#define SB_M1A   384
#define SB_M1B   512
#define SB_CATA  640
#define SB_CATB  768
#define SB_CV4   896   // two 128-blocks (scale64+bias64 each)

// ─── prep kernels ──────────────────────────────────────────────────────────
// fp32 HWIO [tap][ci][co] -> fp16 hi/lo [tap][co][ci]
template<int CIN, int COUT>
__global__ void prep_w(const float* __restrict__ src, u16* dh, u16* dl){
    long long tap = blockIdx.x;
    const float* s = src + tap * CIN * COUT;
    u16* dhp = dh + tap * CIN * COUT;
    u16* dlp = dl + tap * CIN * COUT;
    for (int i = threadIdx.x; i < CIN*COUT; i += blockDim.x) {
        int ci = i / COUT, co = i - ci * COUT;
        float w = s[i];
        __half h = __float2half_rn(w);
        __half l = __float2half_rn(w - __half2float(h));
        dhp[co * CIN + ci] = *(u16*)&h;
        dlp[co * CIN + ci] = *(u16*)&l;
    }
}

__global__ void prep_bn(const float* c1, const float* a0, const float* b0,
                        const float* a1, const float* b1, const float* cat,
                        const float* c4, float* sb){
    int t = threadIdx.x;
    auto seg = [&](int off, const float* s, int C, int stride, int choff){
        for (int c = t; c < C; c += 256) {
            float g = s[choff + c], b = s[stride + choff + c];
            float m = s[2*stride + choff + c], v = s[3*stride + choff + c];
            float sc = g * rsqrtf(v + 1e-3f);
            sb[off + c] = sc; sb[off + C + c] = b - m * sc;
        }
    };
    seg(SB_CV1,  c1, 64, 64, 0);
    seg(SB_M0A,  a0, 64, 64, 0);
    seg(SB_M0B,  b0, 64, 64, 0);
    seg(SB_M1A,  a1, 64, 64, 0);
    seg(SB_M1B,  b1, 64, 64, 0);
    seg(SB_CATA, cat, 64, 128, 0);
    seg(SB_CATB, cat, 64, 128, 64);
    seg(SB_CV4,       c4, 64, 128, 0);    // half 0
    seg(SB_CV4 + 128, c4, 64, 128, 64);   // half 1
}

__global__ void prep_border(u16* th, u16* tl){
    int i = blockIdx.x * blockDim.x + threadIdx.x;
    if (i >= 16 * 644) return;
    int img = i / 644, r = i - img * 644;
    int y, x;
    if      (r < 162) { y = 0;   x = r; }
    else if (r < 324) { y = 161; x = r - 162; }
    else if (r < 484) { x = 0;   y = r - 324 + 1; }
    else              { x = 161; y = r - 484 + 1; }
    long long q = (((long long)img * 162 + y) * 162 + x) * 64;
    uint4 z = make_uint4(0,0,0,0);
    #pragma unroll
    for (int c = 0; c < 8; c++) { *(uint4*)(th + q + c*8) = z; *(uint4*)(tl + q + c*8) = z; }
}

// ─── 1x1 conv GEMM (HMMA, N=64 per block) ─────────────────────────────────
// SRC: 0=fp32 NHWC (split on load)  1=fp16 plane pair  2=concat of two pairs
// OUTM: 0=planes  1=planes padded 162x162  2=fp32 NHWC [p][128] at col offset
// ACT: 0=hswish  1=leaky(0.1)
template<int CIN, int SRC, int OUTM, int ACT>
__global__ void __launch_bounds__(128) g1x1(
    const float* __restrict__ xf,
    const u16* __restrict__ pah, const u16* __restrict__ pal,
    const u16* __restrict__ pbh, const u16* __restrict__ pbl,
    const u16* __restrict__ wh,  const u16* __restrict__ wl,
    const float* __restrict__ sb,
    u16* __restrict__ oh, u16* __restrict__ ol, float* __restrict__ of)
{
    constexpr int STR  = CIN + 8;          // halves per row
    constexpr int ABYT = 128 * STR * 2;
    constexpr int WBYT = 64 * STR * 2;

    extern __shared__ char sm[];
    float* sbs = (float*)sm;
    char* Ah = sm + 512;
    char* Al = Ah + ABYT;
    char* Wh = Al + ABYT;
    char* Wl = Wh + WBYT;

    const int tid = threadIdx.x;
    const int cy  = blockIdx.y;
    const u16* whp = wh + cy * 64 * CIN;
    const u16* wlp = wl + cy * 64 * CIN;
    const float* sbp = sb + cy * 128;
    const int coff = cy * 64;
    const long long p0 = (long long)blockIdx.x * 128;

    for (int c = tid; c < 128; c += 128) sbs[c] = sbp[c];

    constexpr int WC8 = CIN / 8;
    for (int i = tid; i < 64 * WC8; i += 128) {
        int n = i / WC8, c8 = i - n * WC8;
        u32 off = (n * STR + c8 * 8) * 2;
        *(uint4*)(Wh + off) = *(const uint4*)(whp + n * CIN + c8 * 8);
        *(uint4*)(Wl + off) = *(const uint4*)(wlp + n * CIN + c8 * 8);
    }
    for (int i = tid; i < 128 * WC8; i += 128) {
        int row = i / WC8, c8 = i - row * WC8;
        u32 off = (row * STR + c8 * 8) * 2;
        if (SRC == 0) {
            const float* g = xf + (p0 + row) * CIN + c8 * 8;
            float4 f1 = *(const float4*)g, f2 = *(const float4*)(g + 4);
            uint4 H, L;
            sp2(f1.x, f1.y, H.x, L.x); sp2(f1.z, f1.w, H.y, L.y);
            sp2(f2.x, f2.y, H.z, L.z); sp2(f2.z, f2.w, H.w, L.w);
            *(uint4*)(Ah + off) = H; *(uint4*)(Al + off) = L;
        } else if (SRC == 1) {
            *(uint4*)(Ah + off) = *(const uint4*)(pah + (p0 + row) * 64 + c8 * 8);
            *(uint4*)(Al + off) = *(const uint4*)(pal + (p0 + row) * 64 + c8 * 8);
        } else {
            const u16* sh = (c8 < 8) ? pah : pbh;
            const u16* sl = (c8 < 8) ? pal : pbl;
            long long so = (p0 + row) * 64 + (c8 & 7) * 8;
            *(uint4*)(Ah + off) = *(const uint4*)(sh + so);
            *(uint4*)(Al + off) = *(const uint4*)(sl + so);
        }
    }
    __syncthreads();

    const int warp = tid >> 5, lane = tid & 31;
    const int arow  = 32 * warp + (lane & 7) + ((lane & 8) ? 8 : 0);
    const int akoff = (lane & 16) ? 8 : 0;
    const u32 aHb = smem_u32(Ah) + (arow * STR + akoff) * 2;
    const u32 aLb = smem_u32(Al) + (arow * STR + akoff) * 2;
    const int brow  = (lane & 7) + ((lane & 16) ? 8 : 0);
    const int bkoff = (lane & 8) ? 8 : 0;
    const u32 bHb = smem_u32(Wh) + (brow * STR + bkoff) * 2;
    const u32 bLb = smem_u32(Wl) + (brow * STR + bkoff) * 2;

    float acc[2][8][4];
    #pragma unroll
    for (int m = 0; m < 2; m++)
        #pragma unroll
        for (int n = 0; n < 8; n++)
            #pragma unroll
            for (int j = 0; j < 4; j++) acc[m][n][j] = 0.f;

    #pragma unroll
    for (int kc = 0; kc < CIN/16; kc++) {
        u32 ah[2][4], al[2][4];
        ldsm4(aHb + kc*32,               ah[0][0], ah[0][1], ah[0][2], ah[0][3]);
        ldsm4(aHb + kc*32 + 16*STR*2,    ah[1][0], ah[1][1], ah[1][2], ah[1][3]);
        ldsm4(aLb + kc*32,               al[0][0], al[0][1], al[0][2], al[0][3]);
        ldsm4(aLb + kc*32 + 16*STR*2,    al[1][0], al[1][1], al[1][2], al[1][3]);
        #pragma unroll
        for (int jb = 0; jb < 4; jb++) {
            u32 h0, h1, h2, h3, l0, l1, l2, l3;
            ldsm4(bHb + kc*32 + jb*16*STR*2, h0, h1, h2, h3);
            ldsm4(bLb + kc*32 + jb*16*STR*2, l0, l1, l2, l3);
            #pragma unroll
            for (int mt = 0; mt < 2; mt++) {
                mma_(acc[mt][2*jb],   ah[mt], h0, h1);
                mma_(acc[mt][2*jb],   al[mt], h0, h1);
                mma_(acc[mt][2*jb],   ah[mt], l0, l1);
                mma_(acc[mt][2*jb+1], ah[mt], h2, h3);
                mma_(acc[mt][2*jb+1], al[mt], h2, h3);
                mma_(acc[mt][2*jb+1], ah[mt], l2, l3);
            }
        }
    }

    const int gr = lane >> 2, c2l = (lane & 3) * 2;
    float s0[8], s1[8], bb0[8], bb1[8];
    #pragma unroll
    for (int nb = 0; nb < 8; nb++) {
        s0[nb]  = sbs[8*nb + c2l];      s1[nb]  = sbs[8*nb + c2l + 1];
        bb0[nb] = sbs[64 + 8*nb + c2l]; bb1[nb] = sbs[64 + 8*nb + c2l + 1];
    }
    #pragma unroll
    for (int mt = 0; mt < 2; mt++)
    #pragma unroll
    for (int rs = 0; rs < 2; rs++) {
        int row = 32*warp + 16*mt + 8*rs + gr;
        long long p = p0 + row;
        long long q = 0;
        if (OUTM == 0) q = p * 64;
        else if (OUTM == 1) {
            int pi = (int)p;
            int img = pi / 25600, r = pi - img * 25600;
            int y = r / 160, x = r - y * 160;
            q = (((long long)img * 162 + y + 1) * 162 + (x + 1)) * 64;
        }
        #pragma unroll
        for (int nb = 0; nb < 8; nb++) {
            float v0 = s0[nb] * acc[mt][nb][2*rs]     + bb0[nb];
            float v1 = s1[nb] * acc[mt][nb][2*rs + 1] + bb1[nb];
            if (ACT == 0) { v0 = hswish(v0); v1 = hswish(v1); }
            else { v0 = v0 >= 0.f ? v0 : 0.1f*v0; v1 = v1 >= 0.f ? v1 : 0.1f*v1; }
            if (OUTM == 2) {
                *(float2*)(of + p * 128 + coff + 8*nb + c2l) = make_float2(v0, v1);
            } else {
                u32 H, L; sp2(v0, v1, H, L);
                *(u32*)(oh + q + 8*nb + c2l) = H;
                *(u32*)(ol + q + 8*nb + c2l) = L;
            }
        }
    }
}

// ─── 3x3 conv + BN + hswish + residual into y planes ───────────────────────
// tile 8x16 pixels, halo 10x18 staged once; W staged per tap.
__global__ void __launch_bounds__(128) c3x3(
    const u16* __restrict__ th, const u16* __restrict__ tl,
    const u16* __restrict__ wh, const u16* __restrict__ wl,
    const float* __restrict__ sb,
    u16* __restrict__ yh, u16* __restrict__ yl)
{
    constexpr int STR = 72;
    constexpr int ABYT = 180 * STR * 2;   // 25920
    constexpr int WBYT = 64 * STR * 2;    // 9216

    extern __shared__ char sm[];
    float* sbs = (float*)sm;
    char* Ah = sm + 512;
    char* Al = Ah + ABYT;
    char* Wh = Al + ABYT;
    char* Wl = Wh + WBYT;

    const int tid = threadIdx.x;
    const int blk = blockIdx.x;              // 16 imgs * 20 * 10
    const int img = blk / 200, t = blk - img * 200;
    const int ty = t / 10, tx = t - ty * 10;
    const int y0 = ty * 8, x0 = tx * 16;

    for (int c = tid; c < 128; c += 128) sbs[c] = sb[c];

    // halo 10x18 rows x 64ch, both planes (t is pre-padded: no predicates)
    for (int i = tid; i < 180 * 8; i += 128) {
        int hr = i >> 3, c8 = i & 7;
        int hy = hr / 18, hx = hr - hy * 18;
        long long s = (((long long)img * 162 + y0 + hy) * 162 + (x0 + hx)) * 64 + c8 * 8;
        u32 off = (hr * STR + c8 * 8) * 2;
        *(uint4*)(Ah + off) = *(const uint4*)(th + s);
        *(uint4*)(Al + off) = *(const uint4*)(tl + s);
    }

    const int warp = tid >> 5, lane = tid & 31;
    const int arow  = 32 * warp + (lane & 7) + ((lane & 8) ? 8 : 0);
    const int ry0 = arow >> 4, rx = arow & 15;
    const int akoff = (lane & 16) ? 8 : 0;
    const u32 aHbase = smem_u32(Ah);
    const u32 aLbase = smem_u32(Al);
    const int brow  = (lane & 7) + ((lane & 16) ? 8 : 0);
    const int bkoff = (lane & 8) ? 8 : 0;
    const u32 bHb = smem_u32(Wh) + (brow * STR + bkoff) * 2;
    const u32 bLb = smem_u32(Wl) + (brow * STR + bkoff) * 2;

    float acc[2][8][4];
    #pragma unroll
    for (int m = 0; m < 2; m++)
        #pragma unroll
        for (int n = 0; n < 8; n++)
            #pragma unroll
            for (int j = 0; j < 4; j++) acc[m][n][j] = 0.f;

    for (int tap = 0; tap < 9; tap++) {
        __syncthreads();                 // first iter: halo done; later: W reads done
        for (int i = tid; i < 512; i += 128) {
            int n = i >> 3, c8 = i & 7;
            u32 off = (n * STR + c8 * 8) * 2;
            *(uint4*)(Wh + off) = *(const uint4*)(wh + tap*4096 + n*64 + c8*8);
            *(uint4*)(Wl + off) = *(const uint4*)(wl + tap*4096 + n*64 + c8*8);
        }
        __syncthreads();
        const int kh = tap / 3, kw = tap - kh * 3;
        u32 aH[2], aL[2];
        #pragma unroll
        for (int mt = 0; mt < 2; mt++) {
            int hr = (ry0 + mt + kh) * 18 + rx + kw;
            aH[mt] = aHbase + (hr * STR + akoff) * 2;
            aL[mt] = aLbase + (hr * STR + akoff) * 2;
        }
        #pragma unroll
        for (int kc = 0; kc < 4; kc++) {
            u32 ah[2][4], al[2][4];
            ldsm4(aH[0] + kc*32, ah[0][0], ah[0][1], ah[0][2], ah[0][3]);
            ldsm4(aH[1] + kc*32, ah[1][0], ah[1][1], ah[1][2], ah[1][3]);
            ldsm4(aL[0] + kc*32, al[0][0], al[0][1], al[0][2], al[0][3]);
            ldsm4(aL[1] + kc*32, al[1][0], al[1][1], al[1][2], al[1][3]);
            #pragma unroll
            for (int jb = 0; jb < 4; jb++) {
                u32 h0, h1, h2, h3, l0, l1, l2, l3;
                ldsm4(bHb + kc*32 + jb*16*STR*2, h0, h1, h2, h3);
                ldsm4(bLb + kc*32 + jb*16*STR*2, l0, l1, l2, l3);
                #pragma unroll
                for (int mt = 0; mt < 2; mt++) {
                    mma_(acc[mt][2*jb],   ah[mt], h0, h1);
                    mma_(acc[mt][2*jb],   al[mt], h0, h1);
                    mma_(acc[mt][2*jb],   ah[mt], l0, l1);
                    mma_(acc[mt][2*jb+1], ah[mt], h2, h3);
                    mma_(acc[mt][2*jb+1], al[mt], h2, h3);
                    mma_(acc[mt][2*jb+1], ah[mt], l2, l3);
                }
            }
        }
    }

    const int gr = lane >> 2, c2l = (lane & 3) * 2;
    float s0[8], s1[8], bb0[8], bb1[8];
    #pragma unroll
    for (int nb = 0; nb < 8; nb++) {
        s0[nb]  = sbs[8*nb + c2l];      s1[nb]  = sbs[8*nb + c2l + 1];
        bb0[nb] = sbs[64 + 8*nb + c2l]; bb1[nb] = sbs[64 + 8*nb + c2l + 1];
    }
    #pragma unroll
    for (int mt = 0; mt < 2; mt++)
    #pragma unroll
    for (int rs = 0; rs < 2; rs++) {
        int row = 32*warp + 16*mt + 8*rs + gr;
        int yy = row >> 4, xx = row & 15;
        long long q = ((long long)img * 25600 + (y0 + yy) * 160 + (x0 + xx)) * 64;
        #pragma unroll
        for (int nb = 0; nb < 8; nb++) {
            float2 yv0 = dec(*(const u32*)(yh + q + 8*nb + c2l));
            float2 yv1 = dec(*(const u32*)(yl + q + 8*nb + c2l));
            float v0 = s0[nb] * acc[mt][nb][2*rs]     + bb0[nb];
            float v1 = s1[nb] * acc[mt][nb][2*rs + 1] + bb1[nb];
            v0 = hswish(v0) + yv0.x + yv1.x;
            v1 = hswish(v1) + yv0.y + yv1.y;
            u32 H, L; sp2(v0, v1, H, L);
            *(u32*)(yh + q + 8*nb + c2l) = H;
            *(u32*)(yl + q + 8*nb + c2l) = L;
        }
    }
}

// ─── host ──────────────────────────────────────────────────────────────────
extern "C" void kernel_launch(void* const* d_in, const int* in_sizes, int n_in,
                              void* d_out, int out_size)
{
    (void)in_sizes; (void)n_in; (void)out_size;
    const float* x         = (const float*)d_in[0];
    const float* cv1_w     = (const float*)d_in[1];
    const float* cv1_bn    = (const float*)d_in[2];
    const float* m0_cv1_w  = (const float*)d_in[3];
    const float* m0_cv1_bn = (const float*)d_in[4];
    const float* m0_cv2_w  = (const float*)d_in[5];
    const float* m0_cv2_bn = (const float*)d_in[6];
    const float* m1_cv1_w  = (const float*)d_in[7];
    const float* m1_cv1_bn = (const float*)d_in[8];
    const float* m1_cv2_w  = (const float*)d_in[9];
    const float* m1_cv2_bn = (const float*)d_in[10];
    const float* cv3_w     = (const float*)d_in[11];
    const float* cv2p_w    = (const float*)d_in[12];
    const float* bn_cat    = (const float*)d_in[13];
    const float* cv4_w     = (const float*)d_in[14];
    const float* cv4_bn    = (const float*)d_in[15];
    float* out = (float*)d_out;

    u16 *yh, *yl, *ah, *al, *bh, *bl, *th, *tl, *wh, *wl;
    float* sb;
    cudaGetSymbolAddress((void**)&yh, g_yh); cudaGetSymbolAddress((void**)&yl, g_yl);
    cudaGetSymbolAddress((void**)&ah, g_ah); cudaGetSymbolAddress((void**)&al, g_al);
    cudaGetSymbolAddress((void**)&bh, g_bh); cudaGetSymbolAddress((void**)&bl, g_bl);
    cudaGetSymbolAddress((void**)&th, g_th); cudaGetSymbolAddress((void**)&tl, g_tl);
    cudaGetSymbolAddress((void**)&wh, g_wh); cudaGetSymbolAddress((void**)&wl, g_wl);
    cudaGetSymbolAddress((void**)&sb, g_sb);

    constexpr int S64  = 512 + 2*(128*72*2)  + 2*(64*72*2);    // 55808
    constexpr int S128 = 512 + 2*(128*136*2) + 2*(64*136*2);   // 104960
    constexpr int S3   = 512 + 2*(180*72*2)  + 2*(64*72*2);    // 70784

    cudaFuncSetAttribute(g1x1<128,0,0,0>, cudaFuncAttributeMaxDynamicSharedMemorySize, S128);
    cudaFuncSetAttribute(g1x1< 64,1,1,0>, cudaFuncAttributeMaxDynamicSharedMemorySize, S64);
    cudaFuncSetAttribute(g1x1< 64,1,0,1>, cudaFuncAttributeMaxDynamicSharedMemorySize, S64);
    cudaFuncSetAttribute(g1x1<128,0,0,1>, cudaFuncAttributeMaxDynamicSharedMemorySize, S128);
    cudaFuncSetAttribute(g1x1<128,2,2,0>, cudaFuncAttributeMaxDynamicSharedMemorySize, S128);
    cudaFuncSetAttribute(c3x3,            cudaFuncAttributeMaxDynamicSharedMemorySize, S3);

    // prep
    prep_w<128, 64><<<1, 256>>>(cv1_w,    wh + WO_CV1,  wl + WO_CV1);
    prep_w< 64, 64><<<1, 256>>>(m0_cv1_w, wh + WO_M0A,  wl + WO_M0A);
    prep_w< 64, 64><<<9, 256>>>(m0_cv2_w, wh + WO_M0B,  wl + WO_M0B);
    prep_w< 64, 64><<<1, 256>>>(m1_cv1_w, wh + WO_M1A,  wl + WO_M1A);
    prep_w< 64, 64><<<9, 256>>>(m1_cv2_w, wh + WO_M1B,  wl + WO_M1B);
    prep_w< 64, 64><<<1, 256>>>(cv3_w,    wh + WO_CV3,  wl + WO_CV3);
    prep_w<128, 64><<<1, 256>>>(cv2p_w,   wh + WO_CV2P, wl + WO_CV2P);
    prep_w<128,128><<<1, 256>>>(cv4_w,    wh + WO_CV4,  wl + WO_CV4);
    prep_bn<<<1, 256>>>(cv1_bn, m0_cv1_bn, m0_cv2_bn, m1_cv1_bn, m1_cv2_bn, bn_cat, cv4_bn, sb);
    prep_border<<<41, 256>>>(th, tl);

    // cv1: 1x1 128->64 BN+hswish -> y planes
    g1x1<128,0,0,0><<<3200,128,S128>>>(x, 0,0,0,0, wh+WO_CV1, wl+WO_CV1, sb+SB_CV1, yh, yl, 0);
    // bottleneck 0
    g1x1<64,1,1,0><<<3200,128,S64>>>(0, yh,yl,0,0, wh+WO_M0A, wl+WO_M0A, sb+SB_M0A, th, tl, 0);
    c3x3<<<3200,128,S3>>>(th, tl, wh+WO_M0B, wl+WO_M0B, sb+SB_M0B, yh, yl);
    // bottleneck 1
    g1x1<64,1,1,0><<<3200,128,S64>>>(0, yh,yl,0,0, wh+WO_M1A, wl+WO_M1A, sb+SB_M1A, th, tl, 0);
    c3x3<<<3200,128,S3>>>(th, tl, wh+WO_M1B, wl+WO_M1B, sb+SB_M1B, yh, yl);
    // x1 = conv(y, cv3); fold bn_cat[0:64]+leaky -> a planes
    g1x1<64,1,0,1><<<3200,128,S64>>>(0, yh,yl,0,0, wh+WO_CV3, wl+WO_CV3, sb+SB_CATA, ah, al, 0);
    // x2 = conv(x, cv2p); fold bn_cat[64:128]+leaky -> b planes
    g1x1<128,0,0,1><<<3200,128,S128>>>(x, 0,0,0,0, wh+WO_CV2P, wl+WO_CV2P, sb+SB_CATB, bh, bl, 0);
    // cv4: concat(a,b) 128->128 BN+hswish -> out fp32 (two N=64 halves)
    g1x1<128,2,2,0><<<dim3(3200,2),128,S128>>>(0, ah,al, bh,bl, wh+WO_CV4, wl+WO_CV4, sb+SB_CV4, 0, 0, out);
}

// round 5
// speedup vs baseline: 1.7807x; 1.4364x over previous
#include <cuda_runtime.h>
#include <cuda_fp16.h>
#include <cstdint>

typedef unsigned short u16;
typedef unsigned int   u32;

// ─── helpers ───────────────────────────────────────────────────────────────
__device__ __forceinline__ u32 smem_u32(const void* p){
    u32 a;
    asm("{ .reg .u64 t; cvta.to.shared.u64 t, %1; cvt.u32.u64 %0, t; }"
        : "=r"(a) : "l"(p));
    return a;
}
__device__ __forceinline__ void ldsm4(u32 addr, u32& r0, u32& r1, u32& r2, u32& r3){
    asm volatile("ldmatrix.sync.aligned.m8n8.x4.shared.b16 {%0,%1,%2,%3}, [%4];"
        : "=r"(r0), "=r"(r1), "=r"(r2), "=r"(r3) : "r"(addr));
}
__device__ __forceinline__ void mma_(float* c, const u32* a, u32 b0, u32 b1){
    asm volatile("mma.sync.aligned.m16n8k16.row.col.f32.f16.f16.f32 "
        "{%0,%1,%2,%3},{%4,%5,%6,%7},{%8,%9},{%0,%1,%2,%3};"
        : "+f"(c[0]), "+f"(c[1]), "+f"(c[2]), "+f"(c[3])
        : "r"(a[0]), "r"(a[1]), "r"(a[2]), "r"(a[3]), "r"(b0), "r"(b1));
}
#define CPA16(dst, src) \
    asm volatile("cp.async.cg.shared.global [%0], [%1], 16;" :: "r"(dst), "l"(src))
#define CPA_WAIT() do { \
    asm volatile("cp.async.commit_group;" ::: "memory"); \
    asm volatile("cp.async.wait_group 0;" ::: "memory"); } while(0)

__device__ __forceinline__ void sp2(float a, float b, u32& H, u32& L){
    __half2 h = __floats2half2_rn(a, b);
    float2 hf = __half22float2(h);
    __half2 l = __floats2half2_rn(a - hf.x, b - hf.y);
    H = *(u32*)&h; L = *(u32*)&l;
}
__device__ __forceinline__ float2 dec(u32 v){
    __half2 h = *(__half2*)&v; return __half22float2(h);
}
__device__ __forceinline__ float hswish(float x){
    return x * __saturatef((x + 3.0f) * (1.0f / 6.0f));
}

// ─── global scratch ────────────────────────────────────────────────────────
#define PXT 409600
#define TPAD (16*162*162)
#define WTOT 118784

__device__ __align__(16) u16 g_yh[PXT*64], g_yl[PXT*64];
__device__ __align__(16) u16 g_ah[PXT*64], g_al[PXT*64];
__device__ __align__(16) u16 g_bh[PXT*64], g_bl[PXT*64];
__device__ __align__(16) u16 g_th[TPAD*64], g_tl[TPAD*64];
__device__ __align__(16) u16 g_wh[WTOT], g_wl[WTOT];
__device__ float g_sb[1280];

#define WO_CV1   0
#define WO_M0A   8192
#define WO_M0B   12288
#define WO_M1A   49152
#define WO_M1B   53248
#define WO_CV3   90112
#define WO_CV2P  94208
#define WO_CV4   102400

#define SB_CV1   0
#define SB_M0A   128
#define SB_M0B   256
#define SB_M1A   384
#define SB_M1B   512
#define SB_CATA  640
#define SB_CATB  768
#define SB_CV4   896

// ─── single fused prep kernel ──────────────────────────────────────────────
// blocks 0-28: weight transpose+split (4096 elems each)
// block 29:    BN folding
// blocks 30-70: padded-border zeroing
__global__ void prep_all(
    const float* cv1w, const float* m0a, const float* m0b,
    const float* m1a,  const float* m1b, const float* cv3,
    const float* cv2p, const float* cv4,
    const float* c1bn, const float* a0bn, const float* b0bn,
    const float* a1bn, const float* b1bn, const float* catbn, const float* c4bn,
    u16* wh, u16* wl, float* sb, u16* th, u16* tl)
{
    const int bid = blockIdx.x, tid = threadIdx.x;
    if (bid < 29) {
        const float* src; u16 *dh, *dl; int CIN = 64, COUT = 64, b0;
        if      (bid < 2)  { src = cv1w; dh = wh+WO_CV1;  dl = wl+WO_CV1;  CIN = 128; b0 = 0; }
        else if (bid < 3)  { src = m0a;  dh = wh+WO_M0A;  dl = wl+WO_M0A;  b0 = 2; }
        else if (bid < 12) { src = m0b;  dh = wh+WO_M0B;  dl = wl+WO_M0B;  b0 = 3; }
        else if (bid < 13) { src = m1a;  dh = wh+WO_M1A;  dl = wl+WO_M1A;  b0 = 12; }
        else if (bid < 22) { src = m1b;  dh = wh+WO_M1B;  dl = wl+WO_M1B;  b0 = 13; }
        else if (bid < 23) { src = cv3;  dh = wh+WO_CV3;  dl = wl+WO_CV3;  b0 = 22; }
        else if (bid < 25) { src = cv2p; dh = wh+WO_CV2P; dl = wl+WO_CV2P; CIN = 128; b0 = 23; }
        else               { src = cv4;  dh = wh+WO_CV4;  dl = wl+WO_CV4;  CIN = 128; COUT = 128; b0 = 25; }
        const int base = (bid - b0) * 4096;
        const int per = CIN * COUT;
        #pragma unroll 4
        for (int j = 0; j < 16; j++) {
            int e = base + tid + j * 256;
            int tap = e / per, r = e - tap * per;
            int ci = r / COUT, co = r - ci * COUT;
            float w = src[e];
            __half h = __float2half_rn(w);
            __half l = __float2half_rn(w - __half2float(h));
            int d = tap * per + co * CIN + ci;
            dh[d] = *(u16*)&h; dl[d] = *(u16*)&l;
        }
    } else if (bid == 29) {
        auto seg = [&](int off, const float* s, int C, int stride, int choff){
            for (int c = tid; c < C; c += 256) {
                float g = s[choff + c], b = s[stride + choff + c];
                float m = s[2*stride + choff + c], v = s[3*stride + choff + c];
                float sc = g * rsqrtf(v + 1e-3f);
                sb[off + c] = sc; sb[off + C + c] = b - m * sc;
            }
        };
        seg(SB_CV1,  c1bn, 64, 64, 0);
        seg(SB_M0A,  a0bn, 64, 64, 0);
        seg(SB_M0B,  b0bn, 64, 64, 0);
        seg(SB_M1A,  a1bn, 64, 64, 0);
        seg(SB_M1B,  b1bn, 64, 64, 0);
        seg(SB_CATA, catbn, 64, 128, 0);
        seg(SB_CATB, catbn, 64, 128, 64);
        seg(SB_CV4,       c4bn, 64, 128, 0);
        seg(SB_CV4 + 128, c4bn, 64, 128, 64);
    } else {
        int i = (bid - 30) * 256 + tid;
        if (i >= 16 * 644) return;
        int img = i / 644, r = i - img * 644;
        int y, x;
        if      (r < 162) { y = 0;   x = r; }
        else if (r < 324) { y = 161; x = r - 162; }
        else if (r < 484) { x = 0;   y = r - 324 + 1; }
        else              { x = 161; y = r - 484 + 1; }
        long long q = (((long long)img * 162 + y) * 162 + x) * 64;
        uint4 z = make_uint4(0,0,0,0);
        #pragma unroll
        for (int c = 0; c < 8; c++) { *(uint4*)(th + q + c*8) = z; *(uint4*)(tl + q + c*8) = z; }
    }
}

// ─── 1x1 conv GEMM (HMMA), M=256/CTA, N=64, K in 64-ch blocks ──────────────
// SRC: 0=fp32 NHWC (split on load)  1=fp16 plane pair  2=concat of two pairs
// OUTM: 0=planes  1=planes padded 162x162  2=fp32 NHWC [p][128] col offset
// ACT: 0=hswish  1=leaky(0.1)
template<int CIN, int SRC, int OUTM, int ACT>
__global__ void __launch_bounds__(256, 2) g1x1(
    const float* __restrict__ xf,
    const u16* __restrict__ pah, const u16* __restrict__ pal,
    const u16* __restrict__ pbh, const u16* __restrict__ pbl,
    const u16* __restrict__ wh,  const u16* __restrict__ wl,
    const float* __restrict__ sb,
    u16* __restrict__ oh, u16* __restrict__ ol, float* __restrict__ of)
{
    constexpr int KB  = CIN / 64;
    constexpr int STR = 72;
    constexpr int ASZ = 256 * STR * 2;   // 36864
    constexpr int WSZ = 64 * STR * 2;    // 9216

    extern __shared__ char sm[];
    float* sbs = (float*)sm;
    char* Ah = sm + 512;
    char* Al = Ah + ASZ;
    char* Wh = Al + ASZ;
    char* Wl = Wh + WSZ;

    const int tid = threadIdx.x;
    const int cy  = blockIdx.y;
    const u16* whp = wh + cy * 64 * CIN;
    const u16* wlp = wl + cy * 64 * CIN;
    const long long p0 = (long long)blockIdx.x * 256;

    for (int c = tid; c < 128; c += 256) sbs[c] = sb[cy * 128 + c];

    const u32 AhA = smem_u32(Ah), AlA = smem_u32(Al);
    const u32 WhA = smem_u32(Wh), WlA = smem_u32(Wl);

    const int warp = tid >> 5, lane = tid & 31;
    const int arow  = 32 * warp + (lane & 7) + ((lane & 8) ? 8 : 0);
    const int akoff = (lane & 16) ? 8 : 0;
    const u32 aHb = AhA + (arow * STR + akoff) * 2;
    const u32 aLb = AlA + (arow * STR + akoff) * 2;
    const int brow  = (lane & 7) + ((lane & 16) ? 8 : 0);
    const int bkoff = (lane & 8) ? 8 : 0;
    const u32 bHb = WhA + (brow * STR + bkoff) * 2;
    const u32 bLb = WlA + (brow * STR + bkoff) * 2;

    float acc[2][8][4];
    #pragma unroll
    for (int m = 0; m < 2; m++)
        #pragma unroll
        for (int n = 0; n < 8; n++)
            #pragma unroll
            for (int j = 0; j < 4; j++) acc[m][n][j] = 0.f;

    #pragma unroll
    for (int kb = 0; kb < KB; kb++) {
        if (kb) __syncthreads();
        // stage W (64x64 half-block, both planes)
        for (int i = tid; i < 512; i += 256) {
            int n = i >> 3, c8 = i & 7;
            u32 off = (n * STR + c8 * 8) * 2;
            CPA16(WhA + off, whp + n * CIN + kb * 64 + c8 * 8);
            CPA16(WlA + off, wlp + n * CIN + kb * 64 + c8 * 8);
        }
        // stage A (256 rows x 64 ch, both planes)
        for (int i = tid; i < 2048; i += 256) {
            int row = i >> 3, c8 = i & 7;
            u32 off = (row * STR + c8 * 8) * 2;
            if (SRC == 0) {
                const float* g = xf + (p0 + row) * CIN + kb * 64 + c8 * 8;
                float4 f1 = *(const float4*)g, f2 = *(const float4*)(g + 4);
                uint4 H, L;
                sp2(f1.x, f1.y, H.x, L.x); sp2(f1.z, f1.w, H.y, L.y);
                sp2(f2.x, f2.y, H.z, L.z); sp2(f2.z, f2.w, H.w, L.w);
                *(uint4*)(Ah + off) = H; *(uint4*)(Al + off) = L;
            } else if (SRC == 1) {
                CPA16(AhA + off, pah + (p0 + row) * 64 + c8 * 8);
                CPA16(AlA + off, pal + (p0 + row) * 64 + c8 * 8);
            } else {
                const u16* sh = kb ? pbh : pah;
                const u16* sl = kb ? pbl : pal;
                long long so = (p0 + row) * 64 + c8 * 8;
                CPA16(AhA + off, sh + so);
                CPA16(AlA + off, sl + so);
            }
        }
        CPA_WAIT();
        __syncthreads();

        #pragma unroll
        for (int kc = 0; kc < 4; kc++) {
            u32 ah[2][4], al[2][4];
            ldsm4(aHb + kc*32,            ah[0][0], ah[0][1], ah[0][2], ah[0][3]);
            ldsm4(aHb + kc*32 + 16*STR*2, ah[1][0], ah[1][1], ah[1][2], ah[1][3]);
            ldsm4(aLb + kc*32,            al[0][0], al[0][1], al[0][2], al[0][3]);
            ldsm4(aLb + kc*32 + 16*STR*2, al[1][0], al[1][1], al[1][2], al[1][3]);
            #pragma unroll
            for (int jb = 0; jb < 4; jb++) {
                u32 h0, h1, h2, h3, l0, l1, l2, l3;
                ldsm4(bHb + kc*32 + jb*16*STR*2, h0, h1, h2, h3);
                ldsm4(bLb + kc*32 + jb*16*STR*2, l0, l1, l2, l3);
                #pragma unroll
                for (int mt = 0; mt < 2; mt++) {
                    mma_(acc[mt][2*jb],   ah[mt], h0, h1);
                    mma_(acc[mt][2*jb],   al[mt], h0, h1);
                    mma_(acc[mt][2*jb],   ah[mt], l0, l1);
                    mma_(acc[mt][2*jb+1], ah[mt], h2, h3);
                    mma_(acc[mt][2*jb+1], al[mt], h2, h3);
                    mma_(acc[mt][2*jb+1], ah[mt], l2, l3);
                }
            }
        }
    }

    const int gr = lane >> 2, c2l = (lane & 3) * 2;
    float s0[8], s1[8], bb0[8], bb1[8];
    #pragma unroll
    for (int nb = 0; nb < 8; nb++) {
        s0[nb]  = sbs[8*nb + c2l];      s1[nb]  = sbs[8*nb + c2l + 1];
        bb0[nb] = sbs[64 + 8*nb + c2l]; bb1[nb] = sbs[64 + 8*nb + c2l + 1];
    }
    const int coff = cy * 64;
    #pragma unroll
    for (int mt = 0; mt < 2; mt++)
    #pragma unroll
    for (int rs = 0; rs < 2; rs++) {
        int row = 32*warp + 16*mt + 8*rs + gr;
        long long p = p0 + row;
        long long q = 0;
        if (OUTM == 0) q = p * 64;
        else if (OUTM == 1) {
            int pi = (int)p;
            int img = pi / 25600, r = pi - img * 25600;
            int y = r / 160, x = r - y * 160;
            q = (((long long)img * 162 + y + 1) * 162 + (x + 1)) * 64;
        }
        #pragma unroll
        for (int nb = 0; nb < 8; nb++) {
            float v0 = s0[nb] * acc[mt][nb][2*rs]     + bb0[nb];
            float v1 = s1[nb] * acc[mt][nb][2*rs + 1] + bb1[nb];
            if (ACT == 0) { v0 = hswish(v0); v1 = hswish(v1); }
            else { v0 = v0 >= 0.f ? v0 : 0.1f*v0; v1 = v1 >= 0.f ? v1 : 0.1f*v1; }
            if (OUTM == 2) {
                *(float2*)(of + p * 128 + coff + 8*nb + c2l) = make_float2(v0, v1);
            } else {
                u32 H, L; sp2(v0, v1, H, L);
                *(u32*)(oh + q + 8*nb + c2l) = H;
                *(u32*)(ol + q + 8*nb + c2l) = L;
            }
        }
    }
}

// ─── 3x3 conv + BN + hswish + residual into y planes ───────────────────────
// tile 16x16 pixels (M=256), halo 18x18 staged once; W staged per tap.
__global__ void __launch_bounds__(256, 2) c3x3(
    const u16* __restrict__ th, const u16* __restrict__ tl,
    const u16* __restrict__ wh, const u16* __restrict__ wl,
    const float* __restrict__ sb,
    u16* __restrict__ yh, u16* __restrict__ yl)
{
    constexpr int STR = 72;
    constexpr int ASZ = 324 * STR * 2;   // 46656
    constexpr int WSZ = 64 * STR * 2;    // 9216

    extern __shared__ char sm[];
    float* sbs = (float*)sm;
    char* Ah = sm + 512;
    char* Al = Ah + ASZ;
    char* Wh = Al + ASZ;
    char* Wl = Wh + WSZ;

    const int tid = threadIdx.x;
    const int blk = blockIdx.x;              // 16 imgs * 100 tiles
    const int img = blk / 100, t = blk - img * 100;
    const int ty = t / 10, tx = t - ty * 10;
    const int y0 = ty * 16, x0 = tx * 16;

    for (int c = tid; c < 128; c += 256) sbs[c] = sb[c];

    const u32 AhA = smem_u32(Ah), AlA = smem_u32(Al);
    const u32 WhA = smem_u32(Wh), WlA = smem_u32(Wl);

    // halo 18x18 rows x 64ch, both planes (padded input: no predicates)
    for (int i = tid; i < 324 * 8; i += 256) {
        int hr = i >> 3, c8 = i & 7;
        int hy = hr / 18, hx = hr - hy * 18;
        long long s = (((long long)img * 162 + y0 + hy) * 162 + (x0 + hx)) * 64 + c8 * 8;
        u32 off = (hr * STR + c8 * 8) * 2;
        CPA16(AhA + off, th + s);
        CPA16(AlA + off, tl + s);
    }

    const int warp = tid >> 5, lane = tid & 31;
    const int arow  = 32 * warp + (lane & 7) + ((lane & 8) ? 8 : 0);
    const int ry0 = arow >> 4, rx = arow & 15;
    const int akoff = (lane & 16) ? 8 : 0;
    const int brow  = (lane & 7) + ((lane & 16) ? 8 : 0);
    const int bkoff = (lane & 8) ? 8 : 0;
    const u32 bHb = WhA + (brow * STR + bkoff) * 2;
    const u32 bLb = WlA + (brow * STR + bkoff) * 2;

    float acc[2][8][4];
    #pragma unroll
    for (int m = 0; m < 2; m++)
        #pragma unroll
        for (int n = 0; n < 8; n++)
            #pragma unroll
            for (int j = 0; j < 4; j++) acc[m][n][j] = 0.f;

    for (int tap = 0; tap < 9; tap++) {
        if (tap) __syncthreads();            // prior mma reads of W done
        for (int i = tid; i < 512; i += 256) {
            int n = i >> 3, c8 = i & 7;
            u32 off = (n * STR + c8 * 8) * 2;
            CPA16(WhA + off, wh + tap*4096 + n*64 + c8*8);
            CPA16(WlA + off, wl + tap*4096 + n*64 + c8*8);
        }
        CPA_WAIT();                          // tap 0: also drains halo
        __syncthreads();

        const int kh = tap / 3, kw = tap - kh * 3;
        u32 aH[2], aL[2];
        #pragma unroll
        for (int mt = 0; mt < 2; mt++) {
            int hr = (ry0 + mt + kh) * 18 + rx + kw;
            aH[mt] = AhA + (hr * STR + akoff) * 2;
            aL[mt] = AlA + (hr * STR + akoff) * 2;
        }
        #pragma unroll
        for (int kc = 0; kc < 4; kc++) {
            u32 ah[2][4], al[2][4];
            ldsm4(aH[0] + kc*32, ah[0][0], ah[0][1], ah[0][2], ah[0][3]);
            ldsm4(aH[1] + kc*32, ah[1][0], ah[1][1], ah[1][2], ah[1][3]);
            ldsm4(aL[0] + kc*32, al[0][0], al[0][1], al[0][2], al[0][3]);
            ldsm4(aL[1] + kc*32, al[1][0], al[1][1], al[1][2], al[1][3]);
            #pragma unroll
            for (int jb = 0; jb < 4; jb++) {
                u32 h0, h1, h2, h3, l0, l1, l2, l3;
                ldsm4(bHb + kc*32 + jb*16*STR*2, h0, h1, h2, h3);
                ldsm4(bLb + kc*32 + jb*16*STR*2, l0, l1, l2, l3);
                #pragma unroll
                for (int mt = 0; mt < 2; mt++) {
                    mma_(acc[mt][2*jb],   ah[mt], h0, h1);
                    mma_(acc[mt][2*jb],   al[mt], h0, h1);
                    mma_(acc[mt][2*jb],   ah[mt], l0, l1);
                    mma_(acc[mt][2*jb+1], ah[mt], h2, h3);
                    mma_(acc[mt][2*jb+1], al[mt], h2, h3);
                    mma_(acc[mt][2*jb+1], ah[mt], l2, l3);
                }
            }
        }
    }

    const int gr = lane >> 2, c2l = (lane & 3) * 2;
    float s0[8], s1[8], bb0[8], bb1[8];
    #pragma unroll
    for (int nb = 0; nb < 8; nb++) {
        s0[nb]  = sbs[8*nb + c2l];      s1[nb]  = sbs[8*nb + c2l + 1];
        bb0[nb] = sbs[64 + 8*nb + c2l]; bb1[nb] = sbs[64 + 8*nb + c2l + 1];
    }
    #pragma unroll
    for (int mt = 0; mt < 2; mt++)
    #pragma unroll
    for (int rs = 0; rs < 2; rs++) {
        int row = 32*warp + 16*mt + 8*rs + gr;
        int yy = row >> 4, xx = row & 15;
        long long q = ((long long)img * 25600 + (y0 + yy) * 160 + (x0 + xx)) * 64;
        #pragma unroll
        for (int nb = 0; nb < 8; nb++) {
            float2 yv0 = dec(*(const u32*)(yh + q + 8*nb + c2l));
            float2 yv1 = dec(*(const u32*)(yl + q + 8*nb + c2l));
            float v0 = s0[nb] * acc[mt][nb][2*rs]     + bb0[nb];
            float v1 = s1[nb] * acc[mt][nb][2*rs + 1] + bb1[nb];
            v0 = hswish(v0) + yv0.x + yv1.x;
            v1 = hswish(v1) + yv0.y + yv1.y;
            u32 H, L; sp2(v0, v1, H, L);
            *(u32*)(yh + q + 8*nb + c2l) = H;
            *(u32*)(yl + q + 8*nb + c2l) = L;
        }
    }
}

// ─── host ──────────────────────────────────────────────────────────────────
extern "C" void kernel_launch(void* const* d_in, const int* in_sizes, int n_in,
                              void* d_out, int out_size)
{
    (void)in_sizes; (void)n_in; (void)out_size;
    const float* x         = (const float*)d_in[0];
    const float* cv1_w     = (const float*)d_in[1];
    const float* cv1_bn    = (const float*)d_in[2];
    const float* m0_cv1_w  = (const float*)d_in[3];
    const float* m0_cv1_bn = (const float*)d_in[4];
    const float* m0_cv2_w  = (const float*)d_in[5];
    const float* m0_cv2_bn = (const float*)d_in[6];
    const float* m1_cv1_w  = (const float*)d_in[7];
    const float* m1_cv1_bn = (const float*)d_in[8];
    const float* m1_cv2_w  = (const float*)d_in[9];
    const float* m1_cv2_bn = (const float*)d_in[10];
    const float* cv3_w     = (const float*)d_in[11];
    const float* cv2p_w    = (const float*)d_in[12];
    const float* bn_cat    = (const float*)d_in[13];
    const float* cv4_w     = (const float*)d_in[14];
    const float* cv4_bn    = (const float*)d_in[15];
    float* out = (float*)d_out;

    u16 *yh, *yl, *ah, *al, *bh, *bl, *th, *tl, *wh, *wl;
    float* sb;
    cudaGetSymbolAddress((void**)&yh, g_yh); cudaGetSymbolAddress((void**)&yl, g_yl);
    cudaGetSymbolAddress((void**)&ah, g_ah); cudaGetSymbolAddress((void**)&al, g_al);
    cudaGetSymbolAddress((void**)&bh, g_bh); cudaGetSymbolAddress((void**)&bl, g_bl);
    cudaGetSymbolAddress((void**)&th, g_th); cudaGetSymbolAddress((void**)&tl, g_tl);
    cudaGetSymbolAddress((void**)&wh, g_wh); cudaGetSymbolAddress((void**)&wl, g_wl);
    cudaGetSymbolAddress((void**)&sb, g_sb);

    constexpr int S1 = 512 + 2*36864 + 2*9216;   // 92672
    constexpr int S3 = 512 + 2*46656 + 2*9216;   // 112256

    cudaFuncSetAttribute(g1x1<128,0,0,0>, cudaFuncAttributeMaxDynamicSharedMemorySize, S1);
    cudaFuncSetAttribute(g1x1< 64,1,1,0>, cudaFuncAttributeMaxDynamicSharedMemorySize, S1);
    cudaFuncSetAttribute(g1x1< 64,1,0,1>, cudaFuncAttributeMaxDynamicSharedMemorySize, S1);
    cudaFuncSetAttribute(g1x1<128,0,0,1>, cudaFuncAttributeMaxDynamicSharedMemorySize, S1);
    cudaFuncSetAttribute(g1x1<128,2,2,0>, cudaFuncAttributeMaxDynamicSharedMemorySize, S1);
    cudaFuncSetAttribute(c3x3,            cudaFuncAttributeMaxDynamicSharedMemorySize, S3);

    prep_all<<<71, 256>>>(cv1_w, m0_cv1_w, m0_cv2_w, m1_cv1_w, m1_cv2_w,
                          cv3_w, cv2p_w, cv4_w,
                          cv1_bn, m0_cv1_bn, m0_cv2_bn, m1_cv1_bn, m1_cv2_bn,
                          bn_cat, cv4_bn, wh, wl, sb, th, tl);

    // cv1: 1x1 128->64 BN+hswish -> y planes
    g1x1<128,0,0,0><<<1600,256,S1>>>(x, 0,0,0,0, wh+WO_CV1, wl+WO_CV1, sb+SB_CV1, yh, yl, 0);
    // bottleneck 0
    g1x1<64,1,1,0><<<1600,256,S1>>>(0, yh,yl,0,0, wh+WO_M0A, wl+WO_M0A, sb+SB_M0A, th, tl, 0);
    c3x3<<<1600,256,S3>>>(th, tl, wh+WO_M0B, wl+WO_M0B, sb+SB_M0B, yh, yl);
    // bottleneck 1
    g1x1<64,1,1,0><<<1600,256,S1>>>(0, yh,yl,0,0, wh+WO_M1A, wl+WO_M1A, sb+SB_M1A, th, tl, 0);
    c3x3<<<1600,256,S3>>>(th, tl, wh+WO_M1B, wl+WO_M1B, sb+SB_M1B, yh, yl);
    // x1 = conv(y, cv3); fold bn_cat[0:64]+leaky -> a planes
    g1x1<64,1,0,1><<<1600,256,S1>>>(0, yh,yl,0,0, wh+WO_CV3, wl+WO_CV3, sb+SB_CATA, ah, al, 0);
    // x2 = conv(x, cv2p); fold bn_cat[64:128]+leaky -> b planes
    g1x1<128,0,0,1><<<1600,256,S1>>>(x, 0,0,0,0, wh+WO_CV2P, wl+WO_CV2P, sb+SB_CATB, bh, bl, 0);
    // cv4: concat(a,b) 128->128 BN+hswish -> out fp32 (two N=64 halves)
    g1x1<128,2,2,0><<<dim3(1600,2),256,S1>>>(0, ah,al, bh,bl, wh+WO_CV4, wl+WO_CV4, sb+SB_CV4, 0, 0, out);
}

// round 6
// speedup vs baseline: 1.8892x; 1.0610x over previous
#include <cuda_runtime.h>
#include <cuda_fp16.h>
#include <cstdint>

typedef unsigned short u16;
typedef unsigned int   u32;

// ─── helpers ───────────────────────────────────────────────────────────────
__device__ __forceinline__ u32 smem_u32(const void* p){
    u32 a;
    asm("{ .reg .u64 t; cvta.to.shared.u64 t, %1; cvt.u32.u64 %0, t; }"
        : "=r"(a) : "l"(p));
    return a;
}
__device__ __forceinline__ void ldsm4(u32 addr, u32& r0, u32& r1, u32& r2, u32& r3){
    asm volatile("ldmatrix.sync.aligned.m8n8.x4.shared.b16 {%0,%1,%2,%3}, [%4];"
        : "=r"(r0), "=r"(r1), "=r"(r2), "=r"(r3) : "r"(addr));
}
__device__ __forceinline__ void mma_(float* c, const u32* a, u32 b0, u32 b1){
    asm volatile("mma.sync.aligned.m16n8k16.row.col.f32.f16.f16.f32 "
        "{%0,%1,%2,%3},{%4,%5,%6,%7},{%8,%9},{%0,%1,%2,%3};"
        : "+f"(c[0]), "+f"(c[1]), "+f"(c[2]), "+f"(c[3])
        : "r"(a[0]), "r"(a[1]), "r"(a[2]), "r"(a[3]), "r"(b0), "r"(b1));
}
#define CPA16(dst, src) \
    asm volatile("cp.async.cg.shared.global [%0], [%1], 16;" :: "r"(dst), "l"(src))
#define CPA_COMMIT() asm volatile("cp.async.commit_group;" ::: "memory")
#define CPA_WAIT0()  asm volatile("cp.async.wait_group 0;" ::: "memory")
#define CPA_WAIT() do { CPA_COMMIT(); CPA_WAIT0(); } while(0)

__device__ __forceinline__ void sp2(float a, float b, u32& H, u32& L){
    __half2 h = __floats2half2_rn(a, b);
    float2 hf = __half22float2(h);
    __half2 l = __floats2half2_rn(a - hf.x, b - hf.y);
    H = *(u32*)&h; L = *(u32*)&l;
}
__device__ __forceinline__ float2 dec(u32 v){
    __half2 h = *(__half2*)&v; return __half22float2(h);
}
__device__ __forceinline__ float hswish(float x){
    return x * __saturatef((x + 3.0f) * (1.0f / 6.0f));
}

// ─── global scratch ────────────────────────────────────────────────────────
#define PXT 409600
#define TPAD (16*162*162)
#define WTOT 118784

__device__ __align__(16) u16 g_yh[PXT*64], g_yl[PXT*64];
__device__ __align__(16) u16 g_ah[PXT*64], g_al[PXT*64];
__device__ __align__(16) u16 g_bh[PXT*64], g_bl[PXT*64];
__device__ __align__(16) u16 g_th[TPAD*64], g_tl[TPAD*64];
__device__ __align__(16) u16 g_wh[WTOT], g_wl[WTOT];
__device__ float g_sb[1280];

#define WO_CV1   0
#define WO_M0A   8192
#define WO_M0B   12288
#define WO_M1A   49152
#define WO_M1B   53248
#define WO_CV3   90112
#define WO_CV2P  94208
#define WO_CV4   102400

#define SB_CV1   0
#define SB_M0A   128
#define SB_M0B   256
#define SB_M1A   384
#define SB_M1B   512
#define SB_CATA  640
#define SB_CATB  768
#define SB_CV4   896

// ─── single fused prep kernel ──────────────────────────────────────────────
__global__ void prep_all(
    const float* cv1w, const float* m0a, const float* m0b,
    const float* m1a,  const float* m1b, const float* cv3,
    const float* cv2p, const float* cv4,
    const float* c1bn, const float* a0bn, const float* b0bn,
    const float* a1bn, const float* b1bn, const float* catbn, const float* c4bn,
    u16* wh, u16* wl, float* sb, u16* th, u16* tl)
{
    const int bid = blockIdx.x, tid = threadIdx.x;
    if (bid < 29) {
        const float* src; u16 *dh, *dl; int CIN = 64, COUT = 64, b0;
        if      (bid < 2)  { src = cv1w; dh = wh+WO_CV1;  dl = wl+WO_CV1;  CIN = 128; b0 = 0; }
        else if (bid < 3)  { src = m0a;  dh = wh+WO_M0A;  dl = wl+WO_M0A;  b0 = 2; }
        else if (bid < 12) { src = m0b;  dh = wh+WO_M0B;  dl = wl+WO_M0B;  b0 = 3; }
        else if (bid < 13) { src = m1a;  dh = wh+WO_M1A;  dl = wl+WO_M1A;  b0 = 12; }
        else if (bid < 22) { src = m1b;  dh = wh+WO_M1B;  dl = wl+WO_M1B;  b0 = 13; }
        else if (bid < 23) { src = cv3;  dh = wh+WO_CV3;  dl = wl+WO_CV3;  b0 = 22; }
        else if (bid < 25) { src = cv2p; dh = wh+WO_CV2P; dl = wl+WO_CV2P; CIN = 128; b0 = 23; }
        else               { src = cv4;  dh = wh+WO_CV4;  dl = wl+WO_CV4;  CIN = 128; COUT = 128; b0 = 25; }
        const int base = (bid - b0) * 4096;
        const int per = CIN * COUT;
        #pragma unroll 4
        for (int j = 0; j < 16; j++) {
            int e = base + tid + j * 256;
            int tap = e / per, r = e - tap * per;
            int ci = r / COUT, co = r - ci * COUT;
            float w = src[e];
            __half h = __float2half_rn(w);
            __half l = __float2half_rn(w - __half2float(h));
            int d = tap * per + co * CIN + ci;
            dh[d] = *(u16*)&h; dl[d] = *(u16*)&l;
        }
    } else if (bid == 29) {
        auto seg = [&](int off, const float* s, int C, int stride, int choff){
            for (int c = tid; c < C; c += 256) {
                float g = s[choff + c], b = s[stride + choff + c];
                float m = s[2*stride + choff + c], v = s[3*stride + choff + c];
                float sc = g * rsqrtf(v + 1e-3f);
                sb[off + c] = sc; sb[off + C + c] = b - m * sc;
            }
        };
        seg(SB_CV1,  c1bn, 64, 64, 0);
        seg(SB_M0A,  a0bn, 64, 64, 0);
        seg(SB_M0B,  b0bn, 64, 64, 0);
        seg(SB_M1A,  a1bn, 64, 64, 0);
        seg(SB_M1B,  b1bn, 64, 64, 0);
        seg(SB_CATA, catbn, 64, 128, 0);
        seg(SB_CATB, catbn, 64, 128, 64);
        seg(SB_CV4,       c4bn, 64, 128, 0);
        seg(SB_CV4 + 128, c4bn, 64, 128, 64);
    } else {
        int i = (bid - 30) * 256 + tid;
        if (i >= 16 * 644) return;
        int img = i / 644, r = i - img * 644;
        int y, x;
        if      (r < 162) { y = 0;   x = r; }
        else if (r < 324) { y = 161; x = r - 162; }
        else if (r < 484) { x = 0;   y = r - 324 + 1; }
        else              { x = 161; y = r - 484 + 1; }
        long long q = (((long long)img * 162 + y) * 162 + x) * 64;
        uint4 z = make_uint4(0,0,0,0);
        #pragma unroll
        for (int c = 0; c < 8; c++) { *(uint4*)(th + q + c*8) = z; *(uint4*)(tl + q + c*8) = z; }
    }
}

// ─── 1x1 conv GEMM (HMMA), M=256/CTA, N=64, K in 64-ch blocks ──────────────
template<int CIN, int SRC, int OUTM, int ACT>
__global__ void __launch_bounds__(256, 2) g1x1(
    const float* __restrict__ xf,
    const u16* __restrict__ pah, const u16* __restrict__ pal,
    const u16* __restrict__ pbh, const u16* __restrict__ pbl,
    const u16* __restrict__ wh,  const u16* __restrict__ wl,
    const float* __restrict__ sb,
    u16* __restrict__ oh, u16* __restrict__ ol, float* __restrict__ of)
{
    constexpr int KB  = CIN / 64;
    constexpr int STR = 72;
    constexpr int ASZ = 256 * STR * 2;
    constexpr int WSZ = 64 * STR * 2;

    extern __shared__ char sm[];
    float* sbs = (float*)sm;
    char* Ah = sm + 512;
    char* Al = Ah + ASZ;
    char* Wh = Al + ASZ;
    char* Wl = Wh + WSZ;

    const int tid = threadIdx.x;
    const int cy  = blockIdx.y;
    const u16* whp = wh + cy * 64 * CIN;
    const u16* wlp = wl + cy * 64 * CIN;
    const long long p0 = (long long)blockIdx.x * 256;

    for (int c = tid; c < 128; c += 256) sbs[c] = sb[cy * 128 + c];

    const u32 AhA = smem_u32(Ah), AlA = smem_u32(Al);
    const u32 WhA = smem_u32(Wh), WlA = smem_u32(Wl);

    const int warp = tid >> 5, lane = tid & 31;
    const int arow  = 32 * warp + (lane & 7) + ((lane & 8) ? 8 : 0);
    const int akoff = (lane & 16) ? 8 : 0;
    const u32 aHb = AhA + (arow * STR + akoff) * 2;
    const u32 aLb = AlA + (arow * STR + akoff) * 2;
    const int brow  = (lane & 7) + ((lane & 16) ? 8 : 0);
    const int bkoff = (lane & 8) ? 8 : 0;
    const u32 bHb = WhA + (brow * STR + bkoff) * 2;
    const u32 bLb = WlA + (brow * STR + bkoff) * 2;

    float acc[2][8][4];
    #pragma unroll
    for (int m = 0; m < 2; m++)
        #pragma unroll
        for (int n = 0; n < 8; n++)
            #pragma unroll
            for (int j = 0; j < 4; j++) acc[m][n][j] = 0.f;

    #pragma unroll
    for (int kb = 0; kb < KB; kb++) {
        if (kb) __syncthreads();
        for (int i = tid; i < 512; i += 256) {
            int n = i >> 3, c8 = i & 7;
            u32 off = (n * STR + c8 * 8) * 2;
            CPA16(WhA + off, whp + n * CIN + kb * 64 + c8 * 8);
            CPA16(WlA + off, wlp + n * CIN + kb * 64 + c8 * 8);
        }
        for (int i = tid; i < 2048; i += 256) {
            int row = i >> 3, c8 = i & 7;
            u32 off = (row * STR + c8 * 8) * 2;
            if (SRC == 0) {
                const float* g = xf + (p0 + row) * CIN + kb * 64 + c8 * 8;
                float4 f1 = *(const float4*)g, f2 = *(const float4*)(g + 4);
                uint4 H, L;
                sp2(f1.x, f1.y, H.x, L.x); sp2(f1.z, f1.w, H.y, L.y);
                sp2(f2.x, f2.y, H.z, L.z); sp2(f2.z, f2.w, H.w, L.w);
                *(uint4*)(Ah + off) = H; *(uint4*)(Al + off) = L;
            } else if (SRC == 1) {
                CPA16(AhA + off, pah + (p0 + row) * 64 + c8 * 8);
                CPA16(AlA + off, pal + (p0 + row) * 64 + c8 * 8);
            } else {
                const u16* sh = kb ? pbh : pah;
                const u16* sl = kb ? pbl : pal;
                long long so = (p0 + row) * 64 + c8 * 8;
                CPA16(AhA + off, sh + so);
                CPA16(AlA + off, sl + so);
            }
        }
        CPA_WAIT();
        __syncthreads();

        #pragma unroll
        for (int kc = 0; kc < 4; kc++) {
            u32 ah[2][4], al[2][4];
            ldsm4(aHb + kc*32,            ah[0][0], ah[0][1], ah[0][2], ah[0][3]);
            ldsm4(aHb + kc*32 + 16*STR*2, ah[1][0], ah[1][1], ah[1][2], ah[1][3]);
            ldsm4(aLb + kc*32,            al[0][0], al[0][1], al[0][2], al[0][3]);
            ldsm4(aLb + kc*32 + 16*STR*2, al[1][0], al[1][1], al[1][2], al[1][3]);
            #pragma unroll
            for (int jb = 0; jb < 4; jb++) {
                u32 h0, h1, h2, h3, l0, l1, l2, l3;
                ldsm4(bHb + kc*32 + jb*16*STR*2, h0, h1, h2, h3);
                ldsm4(bLb + kc*32 + jb*16*STR*2, l0, l1, l2, l3);
                #pragma unroll
                for (int mt = 0; mt < 2; mt++) {
                    mma_(acc[mt][2*jb],   ah[mt], h0, h1);
                    mma_(acc[mt][2*jb],   al[mt], h0, h1);
                    mma_(acc[mt][2*jb],   ah[mt], l0, l1);
                    mma_(acc[mt][2*jb+1], ah[mt], h2, h3);
                    mma_(acc[mt][2*jb+1], al[mt], h2, h3);
                    mma_(acc[mt][2*jb+1], ah[mt], l2, l3);
                }
            }
        }
    }

    const int gr = lane >> 2, c2l = (lane & 3) * 2;
    float s0[8], s1[8], bb0[8], bb1[8];
    #pragma unroll
    for (int nb = 0; nb < 8; nb++) {
        s0[nb]  = sbs[8*nb + c2l];      s1[nb]  = sbs[8*nb + c2l + 1];
        bb0[nb] = sbs[64 + 8*nb + c2l]; bb1[nb] = sbs[64 + 8*nb + c2l + 1];
    }
    const int coff = cy * 64;
    #pragma unroll
    for (int mt = 0; mt < 2; mt++)
    #pragma unroll
    for (int rs = 0; rs < 2; rs++) {
        int row = 32*warp + 16*mt + 8*rs + gr;
        long long p = p0 + row;
        long long q = 0;
        if (OUTM == 0) q = p * 64;
        else if (OUTM == 1) {
            int pi = (int)p;
            int img = pi / 25600, r = pi - img * 25600;
            int y = r / 160, x = r - y * 160;
            q = (((long long)img * 162 + y + 1) * 162 + (x + 1)) * 64;
        }
        #pragma unroll
        for (int nb = 0; nb < 8; nb++) {
            float v0 = s0[nb] * acc[mt][nb][2*rs]     + bb0[nb];
            float v1 = s1[nb] * acc[mt][nb][2*rs + 1] + bb1[nb];
            if (ACT == 0) { v0 = hswish(v0); v1 = hswish(v1); }
            else { v0 = v0 >= 0.f ? v0 : 0.1f*v0; v1 = v1 >= 0.f ? v1 : 0.1f*v1; }
            if (OUTM == 2) {
                *(float2*)(of + p * 128 + coff + 8*nb + c2l) = make_float2(v0, v1);
            } else {
                u32 H, L; sp2(v0, v1, H, L);
                *(u32*)(oh + q + 8*nb + c2l) = H;
                *(u32*)(ol + q + 8*nb + c2l) = L;
            }
        }
    }
}

// ─── 3x3 conv + BN + hswish + residual, pipelined taps ─────────────────────
// tile 8x16 (M=128), warp = 16x64 tile (one y-row of 16 px), halo 10x18
// staged once; W double-buffered via cp.async: 1 barrier per tap.
__global__ void __launch_bounds__(256, 2) c3x3(
    const u16* __restrict__ th, const u16* __restrict__ tl,
    const u16* __restrict__ wh, const u16* __restrict__ wl,
    const float* __restrict__ sb,
    u16* __restrict__ yh, u16* __restrict__ yl)
{
    constexpr int STR = 72;
    constexpr int APL = 180 * STR * 2;   // 25920 per plane
    constexpr int WPL = 64 * STR * 2;    // 9216  per plane

    extern __shared__ char sm[];
    float* sbs = (float*)sm;
    char* Ah = sm + 512;
    char* Al = Ah + APL;
    char* Wb = Al + APL;                 // [buf][hi|lo], 4 * WPL

    const int tid = threadIdx.x;
    const int blk = blockIdx.x;              // 16 imgs * 200 tiles (20x10)
    const int img = blk / 200, t = blk - img * 200;
    const int ty = t / 10, tx = t - ty * 10;
    const int y0 = ty * 8, x0 = tx * 16;

    for (int c = tid; c < 128; c += 256) sbs[c] = sb[c];

    const u32 AhA = smem_u32(Ah), AlA = smem_u32(Al), WbA = smem_u32(Wb);

    // halo 10x18 rows x 64ch, both planes (padded input: no predicates)
    for (int i = tid; i < 1440; i += 256) {
        int hr = i >> 3, c8 = i & 7;
        int hy = hr / 18, hx = hr - hy * 18;
        long long s = (((long long)img * 162 + y0 + hy) * 162 + (x0 + hx)) * 64 + c8 * 8;
        u32 off = (hr * STR + c8 * 8) * 2;
        CPA16(AhA + off, th + s);
        CPA16(AlA + off, tl + s);
    }
    // W tap 0 -> buf 0
    for (int i = tid; i < 512; i += 256) {
        int n = i >> 3, c8 = i & 7;
        u32 off = (n * STR + c8 * 8) * 2;
        CPA16(WbA + off,       wh + n*64 + c8*8);
        CPA16(WbA + WPL + off, wl + n*64 + c8*8);
    }
    CPA_WAIT();
    __syncthreads();

    const int warp = tid >> 5, lane = tid & 31;
    const int acol  = lane & 15;              // x within 16-wide row
    const int akoff = (lane & 16) ? 8 : 0;
    const int brow  = (lane & 7) + ((lane & 16) ? 8 : 0);
    const int bkoff = (lane & 8) ? 8 : 0;
    const u32 bOff = (brow * STR + bkoff) * 2;

    float acc[8][4];
    #pragma unroll
    for (int n = 0; n < 8; n++)
        #pragma unroll
        for (int j = 0; j < 4; j++) acc[n][j] = 0.f;

    for (int tap = 0; tap < 9; tap++) {
        const int buf = tap & 1;
        // prefetch next tap's W into the other buffer (overlaps MMA below)
        if (tap < 8) {
            const u16* sh = wh + (tap+1)*4096;
            const u16* sl = wl + (tap+1)*4096;
            const u32 WA = WbA + (buf^1)*2*WPL;
            for (int i = tid; i < 512; i += 256) {
                int n = i >> 3, c8 = i & 7;
                u32 off = (n * STR + c8 * 8) * 2;
                CPA16(WA + off,       sh + n*64 + c8*8);
                CPA16(WA + WPL + off, sl + n*64 + c8*8);
            }
            CPA_COMMIT();
        }
        const int kh = tap / 3, kw = tap - kh * 3;
        const int hr = (warp + kh) * 18 + acol + kw;
        const u32 aH = AhA + (hr * STR + akoff) * 2;
        const u32 aL = AlA + (hr * STR + akoff) * 2;
        const u32 bH = WbA + buf*2*WPL + bOff;
        const u32 bL = bH + WPL;
        #pragma unroll
        for (int kc = 0; kc < 4; kc++) {
            u32 ah[4], al[4];
            ldsm4(aH + kc*32, ah[0], ah[1], ah[2], ah[3]);
            ldsm4(aL + kc*32, al[0], al[1], al[2], al[3]);
            #pragma unroll
            for (int jb = 0; jb < 4; jb++) {
                u32 h0, h1, h2, h3, l0, l1, l2, l3;
                ldsm4(bH + kc*32 + jb*16*STR*2, h0, h1, h2, h3);
                ldsm4(bL + kc*32 + jb*16*STR*2, l0, l1, l2, l3);
                mma_(acc[2*jb],   ah, h0, h1);
                mma_(acc[2*jb],   al, h0, h1);
                mma_(acc[2*jb],   ah, l0, l1);
                mma_(acc[2*jb+1], ah, h2, h3);
                mma_(acc[2*jb+1], al, h2, h3);
                mma_(acc[2*jb+1], ah, l2, l3);
            }
        }
        if (tap < 8) {
            CPA_WAIT0();
            __syncthreads();
        }
    }

    const int gr = lane >> 2, c2l = (lane & 3) * 2;
    float s0[8], s1[8], bb0[8], bb1[8];
    #pragma unroll
    for (int nb = 0; nb < 8; nb++) {
        s0[nb]  = sbs[8*nb + c2l];      s1[nb]  = sbs[8*nb + c2l + 1];
        bb0[nb] = sbs[64 + 8*nb + c2l]; bb1[nb] = sbs[64 + 8*nb + c2l + 1];
    }
    #pragma unroll
    for (int rs = 0; rs < 2; rs++) {
        int xx = 8*rs + gr;
        long long q = ((long long)img * 25600 + (y0 + warp) * 160 + (x0 + xx)) * 64;
        #pragma unroll
        for (int nb = 0; nb < 8; nb++) {
            float2 yv0 = dec(*(const u32*)(yh + q + 8*nb + c2l));
            float2 yv1 = dec(*(const u32*)(yl + q + 8*nb + c2l));
            float v0 = s0[nb] * acc[nb][2*rs]     + bb0[nb];
            float v1 = s1[nb] * acc[nb][2*rs + 1] + bb1[nb];
            v0 = hswish(v0) + yv0.x + yv1.x;
            v1 = hswish(v1) + yv0.y + yv1.y;
            u32 H, L; sp2(v0, v1, H, L);
            *(u32*)(yh + q + 8*nb + c2l) = H;
            *(u32*)(yl + q + 8*nb + c2l) = L;
        }
    }
}

// ─── host ──────────────────────────────────────────────────────────────────
extern "C" void kernel_launch(void* const* d_in, const int* in_sizes, int n_in,
                              void* d_out, int out_size)
{
    (void)in_sizes; (void)n_in; (void)out_size;
    const float* x         = (const float*)d_in[0];
    const float* cv1_w     = (const float*)d_in[1];
    const float* cv1_bn    = (const float*)d_in[2];
    const float* m0_cv1_w  = (const float*)d_in[3];
    const float* m0_cv1_bn = (const float*)d_in[4];
    const float* m0_cv2_w  = (const float*)d_in[5];
    const float* m0_cv2_bn = (const float*)d_in[6];
    const float* m1_cv1_w  = (const float*)d_in[7];
    const float* m1_cv1_bn = (const float*)d_in[8];
    const float* m1_cv2_w  = (const float*)d_in[9];
    const float* m1_cv2_bn = (const float*)d_in[10];
    const float* cv3_w     = (const float*)d_in[11];
    const float* cv2p_w    = (const float*)d_in[12];
    const float* bn_cat    = (const float*)d_in[13];
    const float* cv4_w     = (const float*)d_in[14];
    const float* cv4_bn    = (const float*)d_in[15];
    float* out = (float*)d_out;

    u16 *yh, *yl, *ah, *al, *bh, *bl, *th, *tl, *wh, *wl;
    float* sb;
    cudaGetSymbolAddress((void**)&yh, g_yh); cudaGetSymbolAddress((void**)&yl, g_yl);
    cudaGetSymbolAddress((void**)&ah, g_ah); cudaGetSymbolAddress((void**)&al, g_al);
    cudaGetSymbolAddress((void**)&bh, g_bh); cudaGetSymbolAddress((void**)&bl, g_bl);
    cudaGetSymbolAddress((void**)&th, g_th); cudaGetSymbolAddress((void**)&tl, g_tl);
    cudaGetSymbolAddress((void**)&wh, g_wh); cudaGetSymbolAddress((void**)&wl, g_wl);
    cudaGetSymbolAddress((void**)&sb, g_sb);

    constexpr int S1 = 512 + 2*36864 + 2*9216;     // 92672
    constexpr int S3 = 512 + 2*25920 + 4*9216;     // 89216

    cudaFuncSetAttribute(g1x1<128,0,0,0>, cudaFuncAttributeMaxDynamicSharedMemorySize, S1);
    cudaFuncSetAttribute(g1x1< 64,1,1,0>, cudaFuncAttributeMaxDynamicSharedMemorySize, S1);
    cudaFuncSetAttribute(g1x1< 64,1,0,1>, cudaFuncAttributeMaxDynamicSharedMemorySize, S1);
    cudaFuncSetAttribute(g1x1<128,0,0,1>, cudaFuncAttributeMaxDynamicSharedMemorySize, S1);
    cudaFuncSetAttribute(g1x1<128,2,2,0>, cudaFuncAttributeMaxDynamicSharedMemorySize, S1);
    cudaFuncSetAttribute(c3x3,            cudaFuncAttributeMaxDynamicSharedMemorySize, S3);

    prep_all<<<71, 256>>>(cv1_w, m0_cv1_w, m0_cv2_w, m1_cv1_w, m1_cv2_w,
                          cv3_w, cv2p_w, cv4_w,
                          cv1_bn, m0_cv1_bn, m0_cv2_bn, m1_cv1_bn, m1_cv2_bn,
                          bn_cat, cv4_bn, wh, wl, sb, th, tl);

    // cv1: 1x1 128->64 BN+hswish -> y planes
    g1x1<128,0,0,0><<<1600,256,S1>>>(x, 0,0,0,0, wh+WO_CV1, wl+WO_CV1, sb+SB_CV1, yh, yl, 0);
    // bottleneck 0
    g1x1<64,1,1,0><<<1600,256,S1>>>(0, yh,yl,0,0, wh+WO_M0A, wl+WO_M0A, sb+SB_M0A, th, tl, 0);
    c3x3<<<3200,256,S3>>>(th, tl, wh+WO_M0B, wl+WO_M0B, sb+SB_M0B, yh, yl);
    // bottleneck 1
    g1x1<64,1,1,0><<<1600,256,S1>>>(0, yh,yl,0,0, wh+WO_M1A, wl+WO_M1A, sb+SB_M1A, th, tl, 0);
    c3x3<<<3200,256,S3>>>(th, tl, wh+WO_M1B, wl+WO_M1B, sb+SB_M1B, yh, yl);
    // x1 = conv(y, cv3); fold bn_cat[0:64]+leaky -> a planes
    g1x1<64,1,0,1><<<1600,256,S1>>>(0, yh,yl,0,0, wh+WO_CV3, wl+WO_CV3, sb+SB_CATA, ah, al, 0);
    // x2 = conv(x, cv2p); fold bn_cat[64:128]+leaky -> b planes
    g1x1<128,0,0,1><<<1600,256,S1>>>(x, 0,0,0,0, wh+WO_CV2P, wl+WO_CV2P, sb+SB_CATB, bh, bl, 0);
    // cv4: concat(a,b) 128->128 BN+hswish -> out fp32 (two N=64 halves)
    g1x1<128,2,2,0><<<dim3(1600,2),256,S1>>>(0, ah,al, bh,bl, wh+WO_CV4, wl+WO_CV4, sb+SB_CV4, 0, 0, out);
}

// round 7
// speedup vs baseline: 1.8989x; 1.0051x over previous
#include <cuda_runtime.h>
#include <cuda_fp16.h>
#include <cstdint>

typedef unsigned short u16;
typedef unsigned int   u32;

// ─── helpers ───────────────────────────────────────────────────────────────
__device__ __forceinline__ u32 smem_u32(const void* p){
    u32 a;
    asm("{ .reg .u64 t; cvta.to.shared.u64 t, %1; cvt.u32.u64 %0, t; }"
        : "=r"(a) : "l"(p));
    return a;
}
__device__ __forceinline__ void ldsm4(u32 addr, u32& r0, u32& r1, u32& r2, u32& r3){
    asm volatile("ldmatrix.sync.aligned.m8n8.x4.shared.b16 {%0,%1,%2,%3}, [%4];"
        : "=r"(r0), "=r"(r1), "=r"(r2), "=r"(r3) : "r"(addr));
}
__device__ __forceinline__ void mma_(float* c, const u32* a, u32 b0, u32 b1){
    asm volatile("mma.sync.aligned.m16n8k16.row.col.f32.f16.f16.f32 "
        "{%0,%1,%2,%3},{%4,%5,%6,%7},{%8,%9},{%0,%1,%2,%3};"
        : "+f"(c[0]), "+f"(c[1]), "+f"(c[2]), "+f"(c[3])
        : "r"(a[0]), "r"(a[1]), "r"(a[2]), "r"(a[3]), "r"(b0), "r"(b1));
}
#define CPA16(dst, src) \
    asm volatile("cp.async.cg.shared.global [%0], [%1], 16;" :: "r"(dst), "l"(src))
#define CPA_COMMIT()  asm volatile("cp.async.commit_group;" ::: "memory")
#define CPA_WAIT0()   asm volatile("cp.async.wait_group 0;" ::: "memory")
#define CPA_WAIT_G1() asm volatile("cp.async.wait_group 1;" ::: "memory")
#define CPA_WAIT() do { CPA_COMMIT(); CPA_WAIT0(); } while(0)

__device__ __forceinline__ void sp2(float a, float b, u32& H, u32& L){
    __half2 h = __floats2half2_rn(a, b);
    float2 hf = __half22float2(h);
    __half2 l = __floats2half2_rn(a - hf.x, b - hf.y);
    H = *(u32*)&h; L = *(u32*)&l;
}
__device__ __forceinline__ float2 dec(u32 v){
    __half2 h = *(__half2*)&v; return __half22float2(h);
}
__device__ __forceinline__ float hswish(float x){
    return x * __saturatef((x + 3.0f) * (1.0f / 6.0f));
}

// ─── global scratch ────────────────────────────────────────────────────────
#define PXT 409600
#define TPAD (16*162*162)
#define WTOT 118784

__device__ __align__(16) u16 g_yh[PXT*64], g_yl[PXT*64];
__device__ __align__(16) u16 g_ah[PXT*64], g_al[PXT*64];
__device__ __align__(16) u16 g_bh[PXT*64], g_bl[PXT*64];
__device__ __align__(16) u16 g_th[TPAD*64], g_tl[TPAD*64];
__device__ __align__(16) u16 g_wh[WTOT], g_wl[WTOT];
__device__ float g_sb[1280];

#define WO_CV1   0
#define WO_M0A   8192
#define WO_M0B   12288
#define WO_M1A   49152
#define WO_M1B   53248
#define WO_CV3   90112
#define WO_CV2P  94208
#define WO_CV4   102400

#define SB_CV1   0
#define SB_M0A   128
#define SB_M0B   256
#define SB_M1A   384
#define SB_M1B   512
#define SB_CATA  640
#define SB_CATB  768
#define SB_CV4   896

// ─── single fused prep kernel ──────────────────────────────────────────────
__global__ void prep_all(
    const float* cv1w, const float* m0a, const float* m0b,
    const float* m1a,  const float* m1b, const float* cv3,
    const float* cv2p, const float* cv4,
    const float* c1bn, const float* a0bn, const float* b0bn,
    const float* a1bn, const float* b1bn, const float* catbn, const float* c4bn,
    u16* wh, u16* wl, float* sb, u16* th, u16* tl)
{
    const int bid = blockIdx.x, tid = threadIdx.x;
    if (bid < 29) {
        const float* src; u16 *dh, *dl; int CIN = 64, COUT = 64, b0;
        if      (bid < 2)  { src = cv1w; dh = wh+WO_CV1;  dl = wl+WO_CV1;  CIN = 128; b0 = 0; }
        else if (bid < 3)  { src = m0a;  dh = wh+WO_M0A;  dl = wl+WO_M0A;  b0 = 2; }
        else if (bid < 12) { src = m0b;  dh = wh+WO_M0B;  dl = wl+WO_M0B;  b0 = 3; }
        else if (bid < 13) { src = m1a;  dh = wh+WO_M1A;  dl = wl+WO_M1A;  b0 = 12; }
        else if (bid < 22) { src = m1b;  dh = wh+WO_M1B;  dl = wl+WO_M1B;  b0 = 13; }
        else if (bid < 23) { src = cv3;  dh = wh+WO_CV3;  dl = wl+WO_CV3;  b0 = 22; }
        else if (bid < 25) { src = cv2p; dh = wh+WO_CV2P; dl = wl+WO_CV2P; CIN = 128; b0 = 23; }
        else               { src = cv4;  dh = wh+WO_CV4;  dl = wl+WO_CV4;  CIN = 128; COUT = 128; b0 = 25; }
        const int base = (bid - b0) * 4096;
        const int per = CIN * COUT;
        #pragma unroll 4
        for (int j = 0; j < 16; j++) {
            int e = base + tid + j * 256;
            int tap = e / per, r = e - tap * per;
            int ci = r / COUT, co = r - ci * COUT;
            float w = src[e];
            __half h = __float2half_rn(w);
            __half l = __float2half_rn(w - __half2float(h));
            int d = tap * per + co * CIN + ci;
            dh[d] = *(u16*)&h; dl[d] = *(u16*)&l;
        }
    } else if (bid == 29) {
        auto seg = [&](int off, const float* s, int C, int stride, int choff){
            for (int c = tid; c < C; c += 256) {
                float g = s[choff + c], b = s[stride + choff + c];
                float m = s[2*stride + choff + c], v = s[3*stride + choff + c];
                float sc = g * rsqrtf(v + 1e-3f);
                sb[off + c] = sc; sb[off + C + c] = b - m * sc;
            }
        };
        seg(SB_CV1,  c1bn, 64, 64, 0);
        seg(SB_M0A,  a0bn, 64, 64, 0);
        seg(SB_M0B,  b0bn, 64, 64, 0);
        seg(SB_M1A,  a1bn, 64, 64, 0);
        seg(SB_M1B,  b1bn, 64, 64, 0);
        seg(SB_CATA, catbn, 64, 128, 0);
        seg(SB_CATB, catbn, 64, 128, 64);
        seg(SB_CV4,       c4bn, 64, 128, 0);
        seg(SB_CV4 + 128, c4bn, 64, 128, 64);
    } else {
        int i = (bid - 30) * 256 + tid;
        if (i >= 16 * 644) return;
        int img = i / 644, r = i - img * 644;
        int y, x;
        if      (r < 162) { y = 0;   x = r; }
        else if (r < 324) { y = 161; x = r - 162; }
        else if (r < 484) { x = 0;   y = r - 324 + 1; }
        else              { x = 161; y = r - 484 + 1; }
        long long q = (((long long)img * 162 + y) * 162 + x) * 64;
        uint4 z = make_uint4(0,0,0,0);
        #pragma unroll
        for (int c = 0; c < 8; c++) { *(uint4*)(th + q + c*8) = z; *(uint4*)(tl + q + c*8) = z; }
    }
}

// ─── 1x1 conv GEMM (HMMA): persistent CTAs, pipelined A, W preloaded ───────
// M=128/CTA, N=64 (cy selects half for cv4). Stages = (tile, kb).
// SRC: 0=fp32 NHWC (split on load, synchronous)  1=fp16 plane pair  2=concat
// OUTM: 0=planes  1=planes padded 162x162  2=fp32 NHWC [p][128] col offset
// ACT: 0=hswish  1=leaky(0.1)
template<int CIN, int SRC, int OUTM, int ACT>
__global__ void __launch_bounds__(256, 2) g1x1(
    const float* __restrict__ xf,
    const u16* __restrict__ pah, const u16* __restrict__ pal,
    const u16* __restrict__ pbh, const u16* __restrict__ pbl,
    const u16* __restrict__ wh,  const u16* __restrict__ wl,
    const float* __restrict__ sb,
    u16* __restrict__ oh, u16* __restrict__ ol, float* __restrict__ of,
    int ntiles)
{
    constexpr int KB  = CIN / 64;
    constexpr int STR = 72;
    constexpr int APL = 128 * STR * 2;   // 18432 per plane
    constexpr int WPL = 64 * STR * 2;    // 9216  per plane

    extern __shared__ char sm[];
    float* sbs  = (float*)sm;
    char* Wbase = sm + 512;                  // [kb][hi|lo]
    char* Abase = Wbase + KB * 2 * WPL;      // [buf][hi|lo]

    const int tid = threadIdx.x;
    const int cy  = blockIdx.y;
    const u16* whp = wh + cy * 64 * CIN;
    const u16* wlp = wl + cy * 64 * CIN;

    for (int c = tid; c < 128; c += 256) sbs[c] = sb[cy * 128 + c];

    const u32 WA = smem_u32(Wbase), AA = smem_u32(Abase);

    // preload ALL weight k-blocks once (part of group 0)
    #pragma unroll
    for (int kb = 0; kb < KB; kb++)
        for (int i = tid; i < 512; i += 256) {
            int n = i >> 3, c8 = i & 7;
            u32 off = kb * 2 * WPL + (n * STR + c8 * 8) * 2;
            CPA16(WA + off,       whp + n * CIN + kb * 64 + c8 * 8);
            CPA16(WA + off + WPL, wlp + n * CIN + kb * 64 + c8 * 8);
        }

    auto stageA = [&](int t, int kb, int buf){
        long long p0 = (long long)t * 128;
        const u32 AH = AA + buf * 2 * APL;
        char* AB = Abase + buf * 2 * APL;
        for (int i = tid; i < 1024; i += 256) {
            int row = i >> 3, c8 = i & 7;
            u32 off = (row * STR + c8 * 8) * 2;
            if (SRC == 0) {
                const float* g = xf + (p0 + row) * CIN + kb * 64 + c8 * 8;
                float4 f1 = *(const float4*)g, f2 = *(const float4*)(g + 4);
                uint4 H, L;
                sp2(f1.x, f1.y, H.x, L.x); sp2(f1.z, f1.w, H.y, L.y);
                sp2(f2.x, f2.y, H.z, L.z); sp2(f2.z, f2.w, H.w, L.w);
                *(uint4*)(AB + off) = H; *(uint4*)(AB + APL + off) = L;
            } else if (SRC == 1) {
                CPA16(AH + off,       pah + (p0 + row) * CIN + kb * 64 + c8 * 8);
                CPA16(AH + APL + off, pal + (p0 + row) * CIN + kb * 64 + c8 * 8);
            } else {
                const u16* shp = kb ? pbh : pah;
                const u16* slp = kb ? pbl : pal;
                long long so = (p0 + row) * 64 + c8 * 8;
                CPA16(AH + off,       shp + so);
                CPA16(AH + APL + off, slp + so);
            }
        }
    };

    const int warp = tid >> 5, lane = tid & 31;
    const int arow  = 16 * warp + (lane & 7) + ((lane & 8) ? 8 : 0);
    const int akoff = (lane & 16) ? 8 : 0;
    const u32 aOff = (arow * STR + akoff) * 2;
    const int brow  = (lane & 7) + ((lane & 16) ? 8 : 0);
    const int bkoff = (lane & 8) ? 8 : 0;
    const u32 bOff = (brow * STR + bkoff) * 2;

    const int gr = lane >> 2, c2l = (lane & 3) * 2;
    const int coff = cy * 64;

    const int t0 = blockIdx.x;
    if (t0 < ntiles) stageA(t0, 0, 0);
    CPA_COMMIT();

    int buf = 0;
    float acc[8][4];

    for (int t = t0; t < ntiles; t += gridDim.x) {
        #pragma unroll
        for (int n = 0; n < 8; n++)
            #pragma unroll
            for (int j = 0; j < 4; j++) acc[n][j] = 0.f;

        #pragma unroll
        for (int kb = 0; kb < KB; kb++) {
            int nt = t, nkb = kb + 1;
            if (nkb == KB) { nkb = 0; nt = t + gridDim.x; }
            const bool hn = (nt < ntiles);
            if (hn) stageA(nt, nkb, buf ^ 1);
            CPA_COMMIT();
            if (hn) { CPA_WAIT_G1(); } else { CPA_WAIT0(); }
            __syncthreads();

            const u32 aH = AA + buf * 2 * APL + aOff;
            const u32 aL = aH + APL;
            const u32 bH = WA + kb * 2 * WPL + bOff;
            const u32 bL = bH + WPL;

            #pragma unroll
            for (int kc = 0; kc < 4; kc++) {
                u32 ah[4], al[4];
                ldsm4(aH + kc*32, ah[0], ah[1], ah[2], ah[3]);
                ldsm4(aL + kc*32, al[0], al[1], al[2], al[3]);
                #pragma unroll
                for (int jbp = 0; jbp < 2; jbp++) {
                    u32 h[2][4], l[2][4];
                    ldsm4(bH + kc*32 + (2*jbp  )*16*STR*2, h[0][0], h[0][1], h[0][2], h[0][3]);
                    ldsm4(bH + kc*32 + (2*jbp+1)*16*STR*2, h[1][0], h[1][1], h[1][2], h[1][3]);
                    ldsm4(bL + kc*32 + (2*jbp  )*16*STR*2, l[0][0], l[0][1], l[0][2], l[0][3]);
                    ldsm4(bL + kc*32 + (2*jbp+1)*16*STR*2, l[1][0], l[1][1], l[1][2], l[1][3]);
                    float* a0 = acc[4*jbp+0]; float* a1 = acc[4*jbp+1];
                    float* a2 = acc[4*jbp+2]; float* a3 = acc[4*jbp+3];
                    // pass 1: hi*hi (4 independent accs)
                    mma_(a0, ah, h[0][0], h[0][1]); mma_(a1, ah, h[0][2], h[0][3]);
                    mma_(a2, ah, h[1][0], h[1][1]); mma_(a3, ah, h[1][2], h[1][3]);
                    // pass 2: lo*hi
                    mma_(a0, al, h[0][0], h[0][1]); mma_(a1, al, h[0][2], h[0][3]);
                    mma_(a2, al, h[1][0], h[1][1]); mma_(a3, al, h[1][2], h[1][3]);
                    // pass 3: hi*lo
                    mma_(a0, ah, l[0][0], l[0][1]); mma_(a1, ah, l[0][2], l[0][3]);
                    mma_(a2, ah, l[1][0], l[1][1]); mma_(a3, ah, l[1][2], l[1][3]);
                }
            }

            if (kb == KB - 1) {
                #pragma unroll
                for (int rs = 0; rs < 2; rs++) {
                    int row = 16*warp + 8*rs + gr;
                    long long p = (long long)t * 128 + row;
                    long long q = 0;
                    if (OUTM == 0) q = p * 64;
                    else if (OUTM == 1) {
                        int pi = (int)p;
                        int img = pi / 25600, r = pi - img * 25600;
                        int y = r / 160, x = r - y * 160;
                        q = (((long long)img * 162 + y + 1) * 162 + (x + 1)) * 64;
                    }
                    #pragma unroll
                    for (int nb = 0; nb < 8; nb++) {
                        float v0 = sbs[8*nb + c2l]     * acc[nb][2*rs]     + sbs[64 + 8*nb + c2l];
                        float v1 = sbs[8*nb + c2l + 1] * acc[nb][2*rs + 1] + sbs[64 + 8*nb + c2l + 1];
                        if (ACT == 0) { v0 = hswish(v0); v1 = hswish(v1); }
                        else { v0 = v0 >= 0.f ? v0 : 0.1f*v0; v1 = v1 >= 0.f ? v1 : 0.1f*v1; }
                        if (OUTM == 2) {
                            *(float2*)(of + p * 128 + coff + 8*nb + c2l) = make_float2(v0, v1);
                        } else {
                            u32 H, L; sp2(v0, v1, H, L);
                            *(u32*)(oh + q + 8*nb + c2l) = H;
                            *(u32*)(ol + q + 8*nb + c2l) = L;
                        }
                    }
                }
            }
            __syncthreads();
            buf ^= 1;
        }
    }
}

// ─── 3x3 conv + BN + hswish + residual, pipelined taps + reordered MMA ─────
__global__ void __launch_bounds__(256, 2) c3x3(
    const u16* __restrict__ th, const u16* __restrict__ tl,
    const u16* __restrict__ wh, const u16* __restrict__ wl,
    const float* __restrict__ sb,
    u16* __restrict__ yh, u16* __restrict__ yl)
{
    constexpr int STR = 72;
    constexpr int APL = 180 * STR * 2;   // 25920 per plane
    constexpr int WPL = 64 * STR * 2;    // 9216  per plane

    extern __shared__ char sm[];
    float* sbs = (float*)sm;
    char* Ah = sm + 512;
    char* Al = Ah + APL;
    char* Wb = Al + APL;                 // [buf][hi|lo]

    const int tid = threadIdx.x;
    const int blk = blockIdx.x;              // 16 imgs * 200 tiles (20x10)
    const int img = blk / 200, t = blk - img * 200;
    const int ty = t / 10, tx = t - ty * 10;
    const int y0 = ty * 8, x0 = tx * 16;

    for (int c = tid; c < 128; c += 256) sbs[c] = sb[c];

    const u32 AhA = smem_u32(Ah), AlA = smem_u32(Al), WbA = smem_u32(Wb);

    for (int i = tid; i < 1440; i += 256) {
        int hr = i >> 3, c8 = i & 7;
        int hy = hr / 18, hx = hr - hy * 18;
        long long s = (((long long)img * 162 + y0 + hy) * 162 + (x0 + hx)) * 64 + c8 * 8;
        u32 off = (hr * STR + c8 * 8) * 2;
        CPA16(AhA + off, th + s);
        CPA16(AlA + off, tl + s);
    }
    for (int i = tid; i < 512; i += 256) {
        int n = i >> 3, c8 = i & 7;
        u32 off = (n * STR + c8 * 8) * 2;
        CPA16(WbA + off,       wh + n*64 + c8*8);
        CPA16(WbA + WPL + off, wl + n*64 + c8*8);
    }
    CPA_WAIT();
    __syncthreads();

    const int warp = tid >> 5, lane = tid & 31;
    const int acol  = lane & 15;
    const int akoff = (lane & 16) ? 8 : 0;
    const int brow  = (lane & 7) + ((lane & 16) ? 8 : 0);
    const int bkoff = (lane & 8) ? 8 : 0;
    const u32 bOff = (brow * STR + bkoff) * 2;

    float acc[8][4];
    #pragma unroll
    for (int n = 0; n < 8; n++)
        #pragma unroll
        for (int j = 0; j < 4; j++) acc[n][j] = 0.f;

    for (int tap = 0; tap < 9; tap++) {
        const int buf = tap & 1;
        if (tap < 8) {
            const u16* sh = wh + (tap+1)*4096;
            const u16* sl = wl + (tap+1)*4096;
            const u32 WA = WbA + (buf^1)*2*WPL;
            for (int i = tid; i < 512; i += 256) {
                int n = i >> 3, c8 = i & 7;
                u32 off = (n * STR + c8 * 8) * 2;
                CPA16(WA + off,       sh + n*64 + c8*8);
                CPA16(WA + WPL + off, sl + n*64 + c8*8);
            }
            CPA_COMMIT();
        }
        const int kh = tap / 3, kw = tap - kh * 3;
        const int hr = (warp + kh) * 18 + acol + kw;
        const u32 aH = AhA + (hr * STR + akoff) * 2;
        const u32 aL = AlA + (hr * STR + akoff) * 2;
        const u32 bH = WbA + buf*2*WPL + bOff;
        const u32 bL = bH + WPL;
        #pragma unroll
        for (int kc = 0; kc < 4; kc++) {
            u32 ah[4], al[4];
            ldsm4(aH + kc*32, ah[0], ah[1], ah[2], ah[3]);
            ldsm4(aL + kc*32, al[0], al[1], al[2], al[3]);
            #pragma unroll
            for (int jbp = 0; jbp < 2; jbp++) {
                u32 h[2][4], l[2][4];
                ldsm4(bH + kc*32 + (2*jbp  )*16*STR*2, h[0][0], h[0][1], h[0][2], h[0][3]);
                ldsm4(bH + kc*32 + (2*jbp+1)*16*STR*2, h[1][0], h[1][1], h[1][2], h[1][3]);
                ldsm4(bL + kc*32 + (2*jbp  )*16*STR*2, l[0][0], l[0][1], l[0][2], l[0][3]);
                ldsm4(bL + kc*32 + (2*jbp+1)*16*STR*2, l[1][0], l[1][1], l[1][2], l[1][3]);
                float* a0 = acc[4*jbp+0]; float* a1 = acc[4*jbp+1];
                float* a2 = acc[4*jbp+2]; float* a3 = acc[4*jbp+3];
                mma_(a0, ah, h[0][0], h[0][1]); mma_(a1, ah, h[0][2], h[0][3]);
                mma_(a2, ah, h[1][0], h[1][1]); mma_(a3, ah, h[1][2], h[1][3]);
                mma_(a0, al, h[0][0], h[0][1]); mma_(a1, al, h[0][2], h[0][3]);
                mma_(a2, al, h[1][0], h[1][1]); mma_(a3, al, h[1][2], h[1][3]);
                mma_(a0, ah, l[0][0], l[0][1]); mma_(a1, ah, l[0][2], l[0][3]);
                mma_(a2, ah, l[1][0], l[1][1]); mma_(a3, ah, l[1][2], l[1][3]);
            }
        }
        if (tap < 8) {
            CPA_WAIT0();
            __syncthreads();
        }
    }

    const int gr = lane >> 2, c2l = (lane & 3) * 2;
    #pragma unroll
    for (int rs = 0; rs < 2; rs++) {
        int xx = 8*rs + gr;
        long long q = ((long long)img * 25600 + (y0 + warp) * 160 + (x0 + xx)) * 64;
        #pragma unroll
        for (int nb = 0; nb < 8; nb++) {
            float2 yv0 = dec(*(const u32*)(yh + q + 8*nb + c2l));
            float2 yv1 = dec(*(const u32*)(yl + q + 8*nb + c2l));
            float v0 = sbs[8*nb + c2l]     * acc[nb][2*rs]     + sbs[64 + 8*nb + c2l];
            float v1 = sbs[8*nb + c2l + 1] * acc[nb][2*rs + 1] + sbs[64 + 8*nb + c2l + 1];
            v0 = hswish(v0) + yv0.x + yv1.x;
            v1 = hswish(v1) + yv0.y + yv1.y;
            u32 H, L; sp2(v0, v1, H, L);
            *(u32*)(yh + q + 8*nb + c2l) = H;
            *(u32*)(yl + q + 8*nb + c2l) = L;
        }
    }
}

// ─── host ──────────────────────────────────────────────────────────────────
extern "C" void kernel_launch(void* const* d_in, const int* in_sizes, int n_in,
                              void* d_out, int out_size)
{
    (void)in_sizes; (void)n_in; (void)out_size;
    const float* x         = (const float*)d_in[0];
    const float* cv1_w     = (const float*)d_in[1];
    const float* cv1_bn    = (const float*)d_in[2];
    const float* m0_cv1_w  = (const float*)d_in[3];
    const float* m0_cv1_bn = (const float*)d_in[4];
    const float* m0_cv2_w  = (const float*)d_in[5];
    const float* m0_cv2_bn = (const float*)d_in[6];
    const float* m1_cv1_w  = (const float*)d_in[7];
    const float* m1_cv1_bn = (const float*)d_in[8];
    const float* m1_cv2_w  = (const float*)d_in[9];
    const float* m1_cv2_bn = (const float*)d_in[10];
    const float* cv3_w     = (const float*)d_in[11];
    const float* cv2p_w    = (const float*)d_in[12];
    const float* bn_cat    = (const float*)d_in[13];
    const float* cv4_w     = (const float*)d_in[14];
    const float* cv4_bn    = (const float*)d_in[15];
    float* out = (float*)d_out;

    u16 *yh, *yl, *ah, *al, *bh, *bl, *th, *tl, *wh, *wl;
    float* sb;
    cudaGetSymbolAddress((void**)&yh, g_yh); cudaGetSymbolAddress((void**)&yl, g_yl);
    cudaGetSymbolAddress((void**)&ah, g_ah); cudaGetSymbolAddress((void**)&al, g_al);
    cudaGetSymbolAddress((void**)&bh, g_bh); cudaGetSymbolAddress((void**)&bl, g_bl);
    cudaGetSymbolAddress((void**)&th, g_th); cudaGetSymbolAddress((void**)&tl, g_tl);
    cudaGetSymbolAddress((void**)&wh, g_wh); cudaGetSymbolAddress((void**)&wl, g_wl);
    cudaGetSymbolAddress((void**)&sb, g_sb);

    constexpr int S1_64  = 512 + 1*2*9216 + 2*2*18432;   // 92672
    constexpr int S1_128 = 512 + 2*2*9216 + 2*2*18432;   // 111104
    constexpr int S3     = 512 + 2*25920 + 4*9216;       // 89216
    constexpr int NT = 3200;     // 409600 / 128
    constexpr int GP = 304;      // 2 CTAs x 152 SMs

    cudaFuncSetAttribute(g1x1<128,0,0,0>, cudaFuncAttributeMaxDynamicSharedMemorySize, S1_128);
    cudaFuncSetAttribute(g1x1< 64,1,1,0>, cudaFuncAttributeMaxDynamicSharedMemorySize, S1_64);
    cudaFuncSetAttribute(g1x1< 64,1,0,1>, cudaFuncAttributeMaxDynamicSharedMemorySize, S1_64);
    cudaFuncSetAttribute(g1x1<128,0,0,1>, cudaFuncAttributeMaxDynamicSharedMemorySize, S1_128);
    cudaFuncSetAttribute(g1x1<128,2,2,0>, cudaFuncAttributeMaxDynamicSharedMemorySize, S1_128);
    cudaFuncSetAttribute(c3x3,            cudaFuncAttributeMaxDynamicSharedMemorySize, S3);

    prep_all<<<71, 256>>>(cv1_w, m0_cv1_w, m0_cv2_w, m1_cv1_w, m1_cv2_w,
                          cv3_w, cv2p_w, cv4_w,
                          cv1_bn, m0_cv1_bn, m0_cv2_bn, m1_cv1_bn, m1_cv2_bn,
                          bn_cat, cv4_bn, wh, wl, sb, th, tl);

    // cv1: 1x1 128->64 BN+hswish -> y planes
    g1x1<128,0,0,0><<<GP,256,S1_128>>>(x, 0,0,0,0, wh+WO_CV1, wl+WO_CV1, sb+SB_CV1, yh, yl, 0, NT);
    // bottleneck 0
    g1x1<64,1,1,0><<<GP,256,S1_64>>>(0, yh,yl,0,0, wh+WO_M0A, wl+WO_M0A, sb+SB_M0A, th, tl, 0, NT);
    c3x3<<<3200,256,S3>>>(th, tl, wh+WO_M0B, wl+WO_M0B, sb+SB_M0B, yh, yl);
    // bottleneck 1
    g1x1<64,1,1,0><<<GP,256,S1_64>>>(0, yh,yl,0,0, wh+WO_M1A, wl+WO_M1A, sb+SB_M1A, th, tl, 0, NT);
    c3x3<<<3200,256,S3>>>(th, tl, wh+WO_M1B, wl+WO_M1B, sb+SB_M1B, yh, yl);
    // x1 = conv(y, cv3); fold bn_cat[0:64]+leaky -> a planes
    g1x1<64,1,0,1><<<GP,256,S1_64>>>(0, yh,yl,0,0, wh+WO_CV3, wl+WO_CV3, sb+SB_CATA, ah, al, 0, NT);
    // x2 = conv(x, cv2p); fold bn_cat[64:128]+leaky -> b planes
    g1x1<128,0,0,1><<<GP,256,S1_128>>>(x, 0,0,0,0, wh+WO_CV2P, wl+WO_CV2P, sb+SB_CATB, bh, bl, 0, NT);
    // cv4: concat(a,b) 128->128 BN+hswish -> out fp32 (two N=64 halves)
    g1x1<128,2,2,0><<<dim3(GP,2),256,S1_128>>>(0, ah,al, bh,bl, wh+WO_CV4, wl+WO_CV4, sb+SB_CV4, 0, 0, out, NT);
}